// round 2
// baseline (speedup 1.0000x reference)
#include <cuda_runtime.h>
#include <cstdint>

// ---------------------------------------------------------------------------
// Problem constants
//   B=8, C=128, T=16, H=32, W=32  -> S = T*H*W = 16384, HW = 1024
//   M = N = 64, CS = 64
// Output: Z (8,64,16,32,32) then attn (8,64,32,32,16), concatenated f32.
// ---------------------------------------------------------------------------
#define BATCH 8
#define CIN   128
#define S_TOT 16384
#define HW    1024
#define T_DIM 16

// -------------------------- device scratch --------------------------------
__device__ float g_A [BATCH * 64 * S_TOT];   // phi projection      (32 MB)
__device__ float g_B [BATCH * 64 * S_TOT];   // theta proj -> Bm    (32 MB)
__device__ float g_V [BATCH * 64 * S_TOT];   // rho softmax (V)     (32 MB)
__device__ float g_Cm[BATCH * HW];           // condition softmax
__device__ float g_mx[BATCH * 64];           // row max of theta
__device__ float g_is[BATCH * 64];           // 1/sum(exp) of theta
__device__ float g_Pab[32 * BATCH * 64 * 64];// AB_T partials (32 s-chunks)
__device__ float g_AB [BATCH * 64 * 64];     // AB_T reduced

// ---------------------------------------------------------------------------
// K0: condition path.  h1=relu(cond@W1^T+b1); h2=relu(h1@W2^T+b2);
//     Cm = softmax(h2) over 1024.  One block per batch, 1024 threads.
// ---------------------------------------------------------------------------
__global__ void cond_kernel(const float* __restrict__ cond,
                            const float* __restrict__ W1, const float* __restrict__ b1,
                            const float* __restrict__ W2, const float* __restrict__ b2)
{
    const int b   = blockIdx.x;
    const int tid = threadIdx.x;

    __shared__ float cv[64];
    __shared__ float h1[64];
    __shared__ float red[1024];

    if (tid < 64) cv[tid] = cond[b * 64 + tid];
    __syncthreads();

    if (tid < 64) {
        float a = b1[tid];
        #pragma unroll 8
        for (int k = 0; k < 64; k++) a += cv[k] * W1[tid * 64 + k];
        h1[tid] = fmaxf(a, 0.f);
    }
    __syncthreads();

    float a = b2[tid];
    #pragma unroll 8
    for (int k = 0; k < 64; k++) a += h1[k] * W2[tid * 64 + k];
    a = fmaxf(a, 0.f);

    // block softmax over 1024
    red[tid] = a;
    __syncthreads();
    for (int o = 512; o > 0; o >>= 1) {
        if (tid < o) red[tid] = fmaxf(red[tid], red[tid + o]);
        __syncthreads();
    }
    const float m = red[0];
    __syncthreads();

    const float e = __expf(a - m);
    red[tid] = e;
    __syncthreads();
    for (int o = 512; o > 0; o >>= 1) {
        if (tid < o) red[tid] += red[tid + o];
        __syncthreads();
    }
    const float inv = 1.f / red[0];
    g_Cm[b * HW + tid] = e * inv;
}

// ---------------------------------------------------------------------------
// K1: fused projection GEMM.  For a (batch, 128-wide s tile) block:
//   out[192 x 128] = Wcat[192 x 128] @ x[128 x 128]  (+ bias)
//   rows 0..63   -> g_A
//   rows 64..127 -> g_B (raw theta logits)
//   rows 128..191-> channel softmax in-block -> g_V
// Shared: Wsh [c][o] 96 KB, xs [c][s] 64 KB  (rsh aliases Wsh afterwards).
// Threads: 256 = 16(ty: o) x 16(tx: s); register tile 12 x 8.
// ---------------------------------------------------------------------------
#define PROJ_SMEM ((128 * 192 + 128 * 128) * 4)

__global__ void proj_kernel(const float* __restrict__ x,
                            const float* __restrict__ Wphi, const float* __restrict__ bphi,
                            const float* __restrict__ Wth,  const float* __restrict__ bth,
                            const float* __restrict__ Wrho, const float* __restrict__ brho)
{
    extern __shared__ float sh[];
    float* Wsh = sh;                 // [128][192]
    float* xs  = sh + 128 * 192;     // [128][128]
    float* rsh = sh;                 // alias: [64][128] after sync

    const int b   = blockIdx.y;
    const int s0  = blockIdx.x * 128;
    const int tid = threadIdx.x;

    // stage weights (transposed to c-major)
    for (int idx = tid; idx < 192 * 128; idx += 256) {
        const int o = idx >> 7, c = idx & 127;
        float w;
        if (o < 64)       w = Wphi[o * 128 + c];
        else if (o < 128) w = Wth [(o - 64) * 128 + c];
        else              w = Wrho[(o - 128) * 128 + c];
        Wsh[c * 192 + o] = w;
    }
    // stage x tile (global layout is already [c][s], s contiguous)
    const float* xb = x + (size_t)b * CIN * S_TOT + s0;
    for (int idx = tid; idx < 128 * 128; idx += 256) {
        const int c = idx >> 7, s = idx & 127;
        xs[c * 128 + s] = xb[(size_t)c * S_TOT + s];
    }
    __syncthreads();

    const int ty = tid >> 4;   // o base = ty*12
    const int tx = tid & 15;   // s base = tx*8

    float acc[96];
    #pragma unroll
    for (int i = 0; i < 96; i++) acc[i] = 0.f;

    #pragma unroll 2
    for (int c = 0; c < 128; c++) {
        const float4 wA = *(const float4*)(Wsh + c * 192 + ty * 12);
        const float4 wB = *(const float4*)(Wsh + c * 192 + ty * 12 + 4);
        const float4 wC = *(const float4*)(Wsh + c * 192 + ty * 12 + 8);
        const float4 xA = *(const float4*)(xs  + c * 128 + tx * 8);
        const float4 xB = *(const float4*)(xs  + c * 128 + tx * 8 + 4);
        const float wv[12] = {wA.x, wA.y, wA.z, wA.w, wB.x, wB.y, wB.z, wB.w,
                              wC.x, wC.y, wC.z, wC.w};
        const float xv[8]  = {xA.x, xA.y, xA.z, xA.w, xB.x, xB.y, xB.z, xB.w};
        #pragma unroll
        for (int i = 0; i < 12; i++)
            #pragma unroll
            for (int j = 0; j < 8; j++)
                acc[i * 8 + j] = fmaf(wv[i], xv[j], acc[i * 8 + j]);
    }
    __syncthreads();   // Wsh no longer needed; rsh may be written now

    // epilogue: write A / theta, stage rho into rsh
    #pragma unroll
    for (int i = 0; i < 12; i++) {
        const int o = ty * 12 + i;
        if (o < 64) {
            const float bias = bphi[o];
            float* dst = g_A + ((size_t)(b * 64 + o)) * S_TOT + s0 + tx * 8;
            #pragma unroll
            for (int j = 0; j < 8; j++) dst[j] = acc[i * 8 + j] + bias;
        } else if (o < 128) {
            const float bias = bth[o - 64];
            float* dst = g_B + ((size_t)(b * 64 + (o - 64))) * S_TOT + s0 + tx * 8;
            #pragma unroll
            for (int j = 0; j < 8; j++) dst[j] = acc[i * 8 + j] + bias;
        } else {
            const float bias = brho[o - 128];
            #pragma unroll
            for (int j = 0; j < 8; j++)
                rsh[(o - 128) * 128 + tx * 8 + j] = acc[i * 8 + j] + bias;
        }
    }
    __syncthreads();

    // channel softmax over 64 rho rows, one thread per s column
    if (tid < 128) {
        float m = -1e30f;
        #pragma unroll 8
        for (int n = 0; n < 64; n++) m = fmaxf(m, rsh[n * 128 + tid]);
        float sum = 0.f;
        #pragma unroll 8
        for (int n = 0; n < 64; n++) {
            const float e = __expf(rsh[n * 128 + tid] - m);
            rsh[n * 128 + tid] = e;
            sum += e;
        }
        const float inv = 1.f / sum;
        #pragma unroll 8
        for (int n = 0; n < 64; n++)
            g_V[((size_t)(b * 64 + n)) * S_TOT + s0 + tid] = rsh[n * 128 + tid] * inv;
    }
}

// ---------------------------------------------------------------------------
// K2a: per-(b,n) online max / sum-exp over 16384 theta logits.
// ---------------------------------------------------------------------------
__global__ void bstats_kernel()
{
    const int row = blockIdx.x;                 // b*64+n
    const int tid = threadIdx.x;
    const float* p = g_B + (size_t)row * S_TOT;

    float m = -1e30f, s = 0.f;
    for (int i = tid; i < S_TOT; i += 256) {
        const float v = p[i];
        if (v > m) { s = s * __expf(m - v) + 1.f; m = v; }
        else       { s += __expf(v - m); }
    }

    __shared__ float shm[256], shs[256];
    shm[tid] = m; shs[tid] = s;
    __syncthreads();
    for (int o = 128; o > 0; o >>= 1) {
        if (tid < o) {
            const float m2 = shm[tid + o], s2 = shs[tid + o];
            const float M = fmaxf(shm[tid], m2);
            shs[tid] = shs[tid] * __expf(shm[tid] - M) + s2 * __expf(m2 - M);
            shm[tid] = M;
        }
        __syncthreads();
    }
    if (tid == 0) {
        g_mx[row] = shm[0];
        g_is[row] = 1.f / shs[0];
    }
}

// ---------------------------------------------------------------------------
// K2b: Bm = exp(B0-max)/sum (in place) AND attn = transpose(Bm*V, (b,n,hw,t))
// via a 64x16 smem transpose so attn writes are fully coalesced.
// grid (16 hw-tiles, 64 n, 8 b), 128 threads.
// ---------------------------------------------------------------------------
__global__ void bnorm_attn_kernel(float* __restrict__ attn_out)
{
    const int b = blockIdx.z, n = blockIdx.y, hw0 = blockIdx.x * 64;
    const int row = b * 64 + n;
    const float mx  = g_mx[row];
    const float inv = g_is[row];
    float*       Bp = g_B + (size_t)row * S_TOT;
    const float* Vp = g_V + (size_t)row * S_TOT;

    __shared__ float sh[64 * 17];

    for (int i = threadIdx.x; i < 1024; i += 128) {
        const int t  = i >> 6;
        const int hw = i & 63;
        const int s  = t * HW + hw0 + hw;
        const float bm = __expf(Bp[s] - mx) * inv;
        Bp[s] = bm;                         // normalized Bm, reused by K3
        sh[hw * 17 + t] = bm * Vp[s];
    }
    __syncthreads();

    float* out = attn_out + ((size_t)row * HW + hw0) * T_DIM;
    for (int i = threadIdx.x; i < 1024; i += 128)
        out[i] = sh[(i >> 4) * 17 + (i & 15)];
}

// ---------------------------------------------------------------------------
// K3: AB_T partials. grid (32 s-chunks, 8 b), 256 threads.
// Per chunk of 512 s: tile 64 s at a time into smem, 4x4 register tile.
// BC[n,s] = Bm[n,s] * Cm[b, s mod 1024] computed during the staged load.
// ---------------------------------------------------------------------------
__global__ void abt_kernel()
{
    const int b  = blockIdx.y;
    const int ch = blockIdx.x;
    const int sbase = ch * 512;
    const int tid = threadIdx.x;
    const int tm = tid >> 4, tn = tid & 15;

    __shared__ float Ash[64 * 68];   // [ss][m]
    __shared__ float Bsh[64 * 68];   // [ss][n]

    const float* Ab = g_A  + (size_t)b * 64 * S_TOT;
    const float* Bb = g_B  + (size_t)b * 64 * S_TOT;
    const float* Cb = g_Cm + b * HW;

    float acc[16];
    #pragma unroll
    for (int i = 0; i < 16; i++) acc[i] = 0.f;

    for (int st = 0; st < 8; st++) {
        const int s0 = sbase + st * 64;
        __syncthreads();
        for (int idx = tid; idx < 4096; idx += 256) {
            const int scol = idx & 63, r = idx >> 6;
            const int s = s0 + scol;
            Ash[scol * 68 + r] = Ab[(size_t)r * S_TOT + s];
            Bsh[scol * 68 + r] = Bb[(size_t)r * S_TOT + s] * Cb[s & (HW - 1)];
        }
        __syncthreads();
        #pragma unroll 4
        for (int ss = 0; ss < 64; ss++) {
            const float4 a = *(const float4*)(Ash + ss * 68 + tm * 4);
            const float4 c = *(const float4*)(Bsh + ss * 68 + tn * 4);
            const float av[4] = {a.x, a.y, a.z, a.w};
            const float cv[4] = {c.x, c.y, c.z, c.w};
            #pragma unroll
            for (int i = 0; i < 4; i++)
                #pragma unroll
                for (int j = 0; j < 4; j++)
                    acc[i * 4 + j] = fmaf(av[i], cv[j], acc[i * 4 + j]);
        }
    }

    float* P = g_Pab + ((size_t)(ch * 8 + b)) * 4096;
    #pragma unroll
    for (int i = 0; i < 4; i++)
        #pragma unroll
        for (int j = 0; j < 4; j++)
            P[(tm * 4 + i) * 64 + tn * 4 + j] = acc[i * 4 + j];
}

// deterministic reduce over 32 chunks
__global__ void abred_kernel()
{
    const int o = blockIdx.x * 256 + threadIdx.x;   // < 8*64*64 = 32768
    float s = 0.f;
    #pragma unroll 8
    for (int c = 0; c < 32; c++) s += g_Pab[(size_t)c * 32768 + o];
    g_AB[o] = s;
}

// ---------------------------------------------------------------------------
// K4: Z[b,m,s] = sum_n AB[b,m,n] * V[b,n,s].  grid (128 s-tiles, 8 b), 256 thr.
// AB in smem [m][n] (float4 broadcast reads), V tile [n][128].
// ---------------------------------------------------------------------------
__global__ void z_kernel(float* __restrict__ Zout)
{
    const int b  = blockIdx.y;
    const int s0 = blockIdx.x * 128;
    const int tid = threadIdx.x;

    __shared__ float ABsh[64 * 64];    // [m][n]
    __shared__ float Vsh [64 * 128];   // [n][sc]

    for (int idx = tid; idx < 4096; idx += 256)
        ABsh[idx] = g_AB[b * 4096 + idx];
    for (int idx = tid; idx < 64 * 128; idx += 256) {
        const int sc = idx & 127, n = idx >> 7;
        Vsh[n * 128 + sc] = g_V[((size_t)(b * 64 + n)) * S_TOT + s0 + sc];
    }
    __syncthreads();

    const int sc = tid & 127;
    const int mg = tid >> 7;           // 0 or 1 -> m in [mg*32, mg*32+32)

    float acc[32];
    #pragma unroll
    for (int i = 0; i < 32; i++) acc[i] = 0.f;

    for (int n0 = 0; n0 < 64; n0 += 4) {
        const float v0 = Vsh[(n0 + 0) * 128 + sc];
        const float v1 = Vsh[(n0 + 1) * 128 + sc];
        const float v2 = Vsh[(n0 + 2) * 128 + sc];
        const float v3 = Vsh[(n0 + 3) * 128 + sc];
        #pragma unroll
        for (int k = 0; k < 32; k++) {
            const float4 ab = *(const float4*)(ABsh + (mg * 32 + k) * 64 + n0);
            acc[k] = fmaf(ab.x, v0, acc[k]);
            acc[k] = fmaf(ab.y, v1, acc[k]);
            acc[k] = fmaf(ab.z, v2, acc[k]);
            acc[k] = fmaf(ab.w, v3, acc[k]);
        }
    }

    float* Z = Zout + ((size_t)(b * 64 + mg * 32)) * S_TOT + s0 + sc;
    #pragma unroll
    for (int i = 0; i < 32; i++) Z[(size_t)i * S_TOT] = acc[i];
}

// ---------------------------------------------------------------------------
extern "C" void kernel_launch(void* const* d_in, const int* in_sizes, int n_in,
                              void* d_out, int out_size)
{
    (void)in_sizes; (void)n_in; (void)out_size;
    const float* input = (const float*)d_in[0];
    const float* cond  = (const float*)d_in[1];
    const float* Wphi  = (const float*)d_in[2];
    const float* bphi  = (const float*)d_in[3];
    const float* Wth   = (const float*)d_in[4];
    const float* bth   = (const float*)d_in[5];
    const float* Wrho  = (const float*)d_in[6];
    const float* brho  = (const float*)d_in[7];
    const float* W1    = (const float*)d_in[8];
    const float* b1    = (const float*)d_in[9];
    const float* W2    = (const float*)d_in[10];
    const float* b2    = (const float*)d_in[11];

    float* Z    = (float*)d_out;
    float* attn = Z + (size_t)BATCH * 64 * S_TOT;   // second output, concatenated

    cudaFuncSetAttribute(proj_kernel,
                         cudaFuncAttributeMaxDynamicSharedMemorySize, PROJ_SMEM);

    cond_kernel<<<BATCH, 1024>>>(cond, W1, b1, W2, b2);
    proj_kernel<<<dim3(128, BATCH), 256, PROJ_SMEM>>>(input, Wphi, bphi,
                                                      Wth, bth, Wrho, brho);
    bstats_kernel<<<BATCH * 64, 256>>>();
    bnorm_attn_kernel<<<dim3(16, 64, BATCH), 128>>>(attn);
    abt_kernel<<<dim3(32, BATCH), 256>>>();
    abred_kernel<<<128, 256>>>();
    z_kernel<<<dim3(128, BATCH), 256>>>(Z);
}

// round 3
// speedup vs baseline: 1.0634x; 1.0634x over previous
#include <cuda_runtime.h>
#include <cstdint>

// ---------------------------------------------------------------------------
//   B=8, C=128, T=16, H=32, W=32  -> S = T*H*W = 16384, HW = 1024
//   M = N = 64, CS = 64
// Output: Z (8,64,16,32,32) then attn (8,64,32,32,16), concatenated f32.
// ---------------------------------------------------------------------------
#define BATCH 8
#define CIN   128
#define S_TOT 16384
#define HW    1024
#define T_DIM 16

// -------------------------- device scratch --------------------------------
__device__ float g_A [BATCH * 64 * S_TOT];   // phi projection      (32 MB)
__device__ float g_B [BATCH * 64 * S_TOT];   // exp(theta logits)   (32 MB)
__device__ float g_V [BATCH * 64 * S_TOT];   // rho softmax (V)     (32 MB)
__device__ float g_Cm[BATCH * HW];           // condition softmax
__device__ float g_ps[BATCH * 128 * 64];     // per s-tile exp partial sums
__device__ float g_is[BATCH * 64];           // 1/sum(exp theta)
__device__ float g_Pab[32 * BATCH * 64 * 64];// AB_T partials (32 s-chunks)
__device__ float g_AB [BATCH * 64 * 64];     // AB_T reduced

// ---------------------------------------------------------------------------
// K0: condition path. Cm = softmax(relu(relu(cond@W1^T+b1)@W2^T+b2)).
// ---------------------------------------------------------------------------
__global__ void cond_kernel(const float* __restrict__ cond,
                            const float* __restrict__ W1, const float* __restrict__ b1,
                            const float* __restrict__ W2, const float* __restrict__ b2)
{
    const int b   = blockIdx.x;
    const int tid = threadIdx.x;

    __shared__ float cv[64];
    __shared__ float h1[64];
    __shared__ float red[1024];

    if (tid < 64) cv[tid] = cond[b * 64 + tid];
    __syncthreads();

    if (tid < 64) {
        float a = b1[tid];
        #pragma unroll 8
        for (int k = 0; k < 64; k++) a += cv[k] * W1[tid * 64 + k];
        h1[tid] = fmaxf(a, 0.f);
    }
    __syncthreads();

    float a = b2[tid];
    #pragma unroll 8
    for (int k = 0; k < 64; k++) a += h1[k] * W2[tid * 64 + k];
    a = fmaxf(a, 0.f);

    red[tid] = a;
    __syncthreads();
    for (int o = 512; o > 0; o >>= 1) {
        if (tid < o) red[tid] = fmaxf(red[tid], red[tid + o]);
        __syncthreads();
    }
    const float m = red[0];
    __syncthreads();

    const float e = __expf(a - m);
    red[tid] = e;
    __syncthreads();
    for (int o = 512; o > 0; o >>= 1) {
        if (tid < o) red[tid] += red[tid + o];
        __syncthreads();
    }
    const float inv = 1.f / red[0];
    g_Cm[b * HW + tid] = e * inv;
}

// ---------------------------------------------------------------------------
// K1: fused projection GEMM, 192x128 tile per block.
//   rows 0..63   -> g_A (phi + bias)
//   rows 64..127 -> g_B = exp(theta + bias), plus per-(n) tile partial sums
//   rows 128..191-> channel softmax in-block -> g_V
// Shared: Wsh [c][o] 96 KB, xs [c][s] 64 KB (rsh aliases Wsh, part aliases xs).
// ---------------------------------------------------------------------------
#define PROJ_SMEM ((128 * 192 + 128 * 128) * 4)

__global__ void proj_kernel(const float* __restrict__ x,
                            const float* __restrict__ Wphi, const float* __restrict__ bphi,
                            const float* __restrict__ Wth,  const float* __restrict__ bth,
                            const float* __restrict__ Wrho, const float* __restrict__ brho)
{
    extern __shared__ float sh[];
    float* Wsh = sh;                 // [128][192]
    float* xs  = sh + 128 * 192;     // [128][128]
    float* rsh = sh;                 // alias of Wsh after main loop: rho [64][128]
    float* part = xs;                // alias of xs after main loop: [64][16]

    const int b   = blockIdx.y;
    const int s0  = blockIdx.x * 128;
    const int tid = threadIdx.x;

    for (int idx = tid; idx < 192 * 128; idx += 256) {
        const int o = idx >> 7, c = idx & 127;
        float w;
        if (o < 64)       w = Wphi[o * 128 + c];
        else if (o < 128) w = Wth [(o - 64) * 128 + c];
        else              w = Wrho[(o - 128) * 128 + c];
        Wsh[c * 192 + o] = w;
    }
    const float* xb = x + (size_t)b * CIN * S_TOT + s0;
    for (int idx = tid; idx < 128 * 128; idx += 256) {
        const int c = idx >> 7, s = idx & 127;
        xs[c * 128 + s] = xb[(size_t)c * S_TOT + s];
    }
    __syncthreads();

    const int ty = tid >> 4;   // o base = ty*12
    const int tx = tid & 15;   // s base = tx*8

    float acc[96];
    #pragma unroll
    for (int i = 0; i < 96; i++) acc[i] = 0.f;

    #pragma unroll 2
    for (int c = 0; c < 128; c++) {
        const float4 wA = *(const float4*)(Wsh + c * 192 + ty * 12);
        const float4 wB = *(const float4*)(Wsh + c * 192 + ty * 12 + 4);
        const float4 wC = *(const float4*)(Wsh + c * 192 + ty * 12 + 8);
        const float4 xA = *(const float4*)(xs  + c * 128 + tx * 8);
        const float4 xB = *(const float4*)(xs  + c * 128 + tx * 8 + 4);
        const float wv[12] = {wA.x, wA.y, wA.z, wA.w, wB.x, wB.y, wB.z, wB.w,
                              wC.x, wC.y, wC.z, wC.w};
        const float xv[8]  = {xA.x, xA.y, xA.z, xA.w, xB.x, xB.y, xB.z, xB.w};
        #pragma unroll
        for (int i = 0; i < 12; i++)
            #pragma unroll
            for (int j = 0; j < 8; j++)
                acc[i * 8 + j] = fmaf(wv[i], xv[j], acc[i * 8 + j]);
    }
    __syncthreads();   // Wsh/xs dead -> rsh/part writable

    #pragma unroll
    for (int i = 0; i < 12; i++) {
        const int o = ty * 12 + i;
        if (o < 64) {
            const float bias = bphi[o];
            float* dst = g_A + ((size_t)(b * 64 + o)) * S_TOT + s0 + tx * 8;
            #pragma unroll
            for (int j = 0; j < 8; j++) dst[j] = acc[i * 8 + j] + bias;
        } else if (o < 128) {
            const float bias = bth[o - 64];
            float* dst = g_B + ((size_t)(b * 64 + (o - 64))) * S_TOT + s0 + tx * 8;
            float ps = 0.f;
            #pragma unroll
            for (int j = 0; j < 8; j++) {
                const float e = __expf(acc[i * 8 + j] + bias);
                dst[j] = e;
                ps += e;
            }
            part[(o - 64) * 16 + tx] = ps;
        } else {
            const float bias = brho[o - 128];
            #pragma unroll
            for (int j = 0; j < 8; j++)
                rsh[(o - 128) * 128 + tx * 8 + j] = acc[i * 8 + j] + bias;
        }
    }
    __syncthreads();

    if (tid < 128) {
        // rho channel softmax, one thread per s column
        float m = -1e30f;
        #pragma unroll 8
        for (int n = 0; n < 64; n++) m = fmaxf(m, rsh[n * 128 + tid]);
        float sum = 0.f;
        #pragma unroll 8
        for (int n = 0; n < 64; n++) {
            const float e = __expf(rsh[n * 128 + tid] - m);
            rsh[n * 128 + tid] = e;
            sum += e;
        }
        const float inv = 1.f / sum;
        #pragma unroll 8
        for (int n = 0; n < 64; n++)
            g_V[((size_t)(b * 64 + n)) * S_TOT + s0 + tid] = rsh[n * 128 + tid] * inv;
    } else if (tid < 192) {
        // theta exp-sum partial for this tile
        const int n = tid - 128;
        float s = 0.f;
        #pragma unroll
        for (int k = 0; k < 16; k++) s += part[n * 16 + k];
        g_ps[((size_t)(b * 128 + blockIdx.x)) * 64 + n] = s;
    }
}

// ---------------------------------------------------------------------------
// K2: reduce tile partial sums -> g_is = 1/sum. One warp per (b,n) row.
// ---------------------------------------------------------------------------
__global__ void esum_kernel()
{
    const int row  = blockIdx.x * 8 + (threadIdx.x >> 5);   // 64 blocks x 8 warps
    const int lane = threadIdx.x & 31;
    const int b = row >> 6, n = row & 63;
    const float* p = g_ps + (size_t)b * 128 * 64 + n;

    float s = 0.f;
    #pragma unroll
    for (int t = lane; t < 128; t += 32) s += p[t * 64];
    #pragma unroll
    for (int o = 16; o > 0; o >>= 1) s += __shfl_down_sync(0xffffffffu, s, o);
    if (lane == 0) g_is[row] = 1.f / s;
}

// ---------------------------------------------------------------------------
// K3: attn = transpose(Bm*V) with Bm = e*inv.
// One block per (row, hw-quarter of 256). 256 threads, float4 throughout.
// smem [hw 256][t 16] with pad to 20 (keeps float4 alignment both ways).
// ---------------------------------------------------------------------------
__global__ void attn_kernel(float* __restrict__ attn_out)
{
    const int row = blockIdx.x >> 2;
    const int hw0 = (blockIdx.x & 3) * 256;
    const int tid = threadIdx.x;
    const float inv = g_is[row];

    const float4* e4 = (const float4*)(g_B + (size_t)row * S_TOT);
    const float4* v4 = (const float4*)(g_V + (size_t)row * S_TOT);

    __shared__ float sh[256 * 20];

    #pragma unroll
    for (int k = 0; k < 4; k++) {
        const int id = k * 256 + tid;          // 1024 float4 slots: 16 t x 64 hw4
        const int t  = id >> 6;
        const int f  = id & 63;
        const int si = (t << 10) + hw0 + f * 4;
        const float4 ev = e4[si >> 2];
        const float4 vv = v4[si >> 2];
        float* d = sh + (f * 4) * 20 + t;
        d[0]  = ev.x * vv.x * inv;
        d[20] = ev.y * vv.y * inv;
        d[40] = ev.z * vv.z * inv;
        d[60] = ev.w * vv.w * inv;
    }
    __syncthreads();

    float4* out = (float4*)(attn_out + ((size_t)row * HW + hw0) * T_DIM);
    #pragma unroll
    for (int k = 0; k < 4; k++) {
        const int id = k * 256 + tid;          // 1024 float4 of output
        const int hw = id >> 2;
        const int tc = (id & 3) * 4;
        out[id] = *(const float4*)(sh + hw * 20 + tc);
    }
}

// ---------------------------------------------------------------------------
// K4: AB_T partials. grid (32 s-chunks, 8 b), 256 threads.
// BC[n,s] = e[n,s] * inv[n] * Cm[b, s mod 1024] applied at staging time.
// ---------------------------------------------------------------------------
__global__ void abt_kernel()
{
    const int b  = blockIdx.y;
    const int ch = blockIdx.x;
    const int sbase = ch * 512;
    const int tid = threadIdx.x;
    const int tm = tid >> 4, tn = tid & 15;

    __shared__ float Ash[64 * 68];   // [ss][m]
    __shared__ float Bsh[64 * 68];   // [ss][n]
    __shared__ float invsh[64];
    __shared__ float Csh[HW];

    const float* Ab = g_A  + (size_t)b * 64 * S_TOT;
    const float* Bb = g_B  + (size_t)b * 64 * S_TOT;

    if (tid < 64) invsh[tid] = g_is[b * 64 + tid];
    for (int i = tid; i < HW; i += 256) Csh[i] = g_Cm[b * HW + i];

    float acc[16];
    #pragma unroll
    for (int i = 0; i < 16; i++) acc[i] = 0.f;

    for (int st = 0; st < 8; st++) {
        const int s0 = sbase + st * 64;
        __syncthreads();
        for (int idx = tid; idx < 4096; idx += 256) {
            const int scol = idx & 63, r = idx >> 6;
            const int s = s0 + scol;
            Ash[scol * 68 + r] = Ab[(size_t)r * S_TOT + s];
            Bsh[scol * 68 + r] = Bb[(size_t)r * S_TOT + s] * invsh[r] * Csh[s & (HW - 1)];
        }
        __syncthreads();
        #pragma unroll 4
        for (int ss = 0; ss < 64; ss++) {
            const float4 a = *(const float4*)(Ash + ss * 68 + tm * 4);
            const float4 c = *(const float4*)(Bsh + ss * 68 + tn * 4);
            const float av[4] = {a.x, a.y, a.z, a.w};
            const float cv[4] = {c.x, c.y, c.z, c.w};
            #pragma unroll
            for (int i = 0; i < 4; i++)
                #pragma unroll
                for (int j = 0; j < 4; j++)
                    acc[i * 4 + j] = fmaf(av[i], cv[j], acc[i * 4 + j]);
        }
    }

    float* P = g_Pab + ((size_t)(ch * 8 + b)) * 4096;
    #pragma unroll
    for (int i = 0; i < 4; i++)
        #pragma unroll
        for (int j = 0; j < 4; j++)
            P[(tm * 4 + i) * 64 + tn * 4 + j] = acc[i * 4 + j];
}

// deterministic reduce over 32 chunks
__global__ void abred_kernel()
{
    const int o = blockIdx.x * 256 + threadIdx.x;   // < 32768
    float s = 0.f;
    #pragma unroll 8
    for (int c = 0; c < 32; c++) s += g_Pab[(size_t)c * 32768 + o];
    g_AB[o] = s;
}

// ---------------------------------------------------------------------------
// K5: Z[b,m,s] = sum_n AB[b,m,n] * V[b,n,s].
// ---------------------------------------------------------------------------
__global__ void z_kernel(float* __restrict__ Zout)
{
    const int b  = blockIdx.y;
    const int s0 = blockIdx.x * 128;
    const int tid = threadIdx.x;

    __shared__ float ABsh[64 * 64];    // [m][n]
    __shared__ float Vsh [64 * 128];   // [n][sc]

    for (int idx = tid; idx < 4096; idx += 256)
        ABsh[idx] = g_AB[b * 4096 + idx];
    for (int idx = tid; idx < 64 * 128; idx += 256) {
        const int sc = idx & 127, n = idx >> 7;
        Vsh[n * 128 + sc] = g_V[((size_t)(b * 64 + n)) * S_TOT + s0 + sc];
    }
    __syncthreads();

    const int sc = tid & 127;
    const int mg = tid >> 7;

    float acc[32];
    #pragma unroll
    for (int i = 0; i < 32; i++) acc[i] = 0.f;

    for (int n0 = 0; n0 < 64; n0 += 4) {
        const float v0 = Vsh[(n0 + 0) * 128 + sc];
        const float v1 = Vsh[(n0 + 1) * 128 + sc];
        const float v2 = Vsh[(n0 + 2) * 128 + sc];
        const float v3 = Vsh[(n0 + 3) * 128 + sc];
        #pragma unroll
        for (int k = 0; k < 32; k++) {
            const float4 ab = *(const float4*)(ABsh + (mg * 32 + k) * 64 + n0);
            acc[k] = fmaf(ab.x, v0, acc[k]);
            acc[k] = fmaf(ab.y, v1, acc[k]);
            acc[k] = fmaf(ab.z, v2, acc[k]);
            acc[k] = fmaf(ab.w, v3, acc[k]);
        }
    }

    float* Z = Zout + ((size_t)(b * 64 + mg * 32)) * S_TOT + s0 + sc;
    #pragma unroll
    for (int i = 0; i < 32; i++) Z[(size_t)i * S_TOT] = acc[i];
}

// ---------------------------------------------------------------------------
extern "C" void kernel_launch(void* const* d_in, const int* in_sizes, int n_in,
                              void* d_out, int out_size)
{
    (void)in_sizes; (void)n_in; (void)out_size;
    const float* input = (const float*)d_in[0];
    const float* cond  = (const float*)d_in[1];
    const float* Wphi  = (const float*)d_in[2];
    const float* bphi  = (const float*)d_in[3];
    const float* Wth   = (const float*)d_in[4];
    const float* bth   = (const float*)d_in[5];
    const float* Wrho  = (const float*)d_in[6];
    const float* brho  = (const float*)d_in[7];
    const float* W1    = (const float*)d_in[8];
    const float* b1    = (const float*)d_in[9];
    const float* W2    = (const float*)d_in[10];
    const float* b2    = (const float*)d_in[11];

    float* Z    = (float*)d_out;
    float* attn = Z + (size_t)BATCH * 64 * S_TOT;

    cudaFuncSetAttribute(proj_kernel,
                         cudaFuncAttributeMaxDynamicSharedMemorySize, PROJ_SMEM);

    cond_kernel<<<BATCH, 1024>>>(cond, W1, b1, W2, b2);
    proj_kernel<<<dim3(128, BATCH), 256, PROJ_SMEM>>>(input, Wphi, bphi,
                                                      Wth, bth, Wrho, brho);
    esum_kernel<<<64, 256>>>();
    attn_kernel<<<512 * 4, 256>>>(attn);
    abt_kernel<<<dim3(32, BATCH), 256>>>();
    abred_kernel<<<128, 256>>>();
    z_kernel<<<dim3(128, BATCH), 256>>>(Z);
}

// round 5
// speedup vs baseline: 1.7954x; 1.6883x over previous
#include <cuda_runtime.h>
#include <cuda_bf16.h>
#include <cstdint>

// ---------------------------------------------------------------------------
//   B=8, C=128, T=16, H=32, W=32  -> S = 16384, HW = 1024
//   M = N = 64, CS = 64.  Output: Z (8,64,16,32,32) ++ attn (8,64,32,32,16).
// ---------------------------------------------------------------------------
#define BATCH 8
#define CIN   128
#define S_TOT 16384
#define HW    1024
#define T_DIM 16
#define NOUT  192

// -------------------------- device scratch --------------------------------
__device__ float g_A [BATCH * 64 * S_TOT];
__device__ float g_B [BATCH * 64 * S_TOT];    // exp(theta logits)
__device__ float g_V [BATCH * 64 * S_TOT];
__device__ float g_Cm[BATCH * HW];
__device__ float g_ps[BATCH * 128 * 64];
__device__ float g_is[BATCH * 64];
__device__ float g_Pab[32 * BATCH * 64 * 64];
__device__ float g_AB [BATCH * 64 * 64];
// weights pre-split to bf16 hi/lo, packed pairs of c: [o][64] uint32
__device__ uint32_t g_Whb[NOUT * 64];
__device__ uint32_t g_Wlb[NOUT * 64];
__device__ float    g_bias[NOUT];

// ------------------------------ helpers -----------------------------------
__device__ __forceinline__ uint32_t smem_u32(const void* p) {
    uint32_t a;
    asm("{ .reg .u64 t; cvta.to.shared.u64 t, %1; cvt.u32.u64 %0, t; }"
        : "=r"(a) : "l"(p));
    return a;
}

#define LDSM_X4(r, addr) \
    asm volatile("ldmatrix.sync.aligned.m8n8.x4.shared.b16 {%0,%1,%2,%3}, [%4];" \
        : "=r"((r)[0]), "=r"((r)[1]), "=r"((r)[2]), "=r"((r)[3]) : "r"(addr))
#define LDSM_X2(r0, r1, addr) \
    asm volatile("ldmatrix.sync.aligned.m8n8.x2.shared.b16 {%0,%1}, [%2];" \
        : "=r"(r0), "=r"(r1) : "r"(addr))

__device__ __forceinline__ void mma_bf16(float* c, const uint32_t* a,
                                         uint32_t b0, uint32_t b1) {
    asm volatile(
        "mma.sync.aligned.m16n8k16.row.col.f32.bf16.bf16.f32 "
        "{%0,%1,%2,%3}, {%4,%5,%6,%7}, {%8,%9}, {%0,%1,%2,%3};"
        : "+f"(c[0]), "+f"(c[1]), "+f"(c[2]), "+f"(c[3])
        : "r"(a[0]), "r"(a[1]), "r"(a[2]), "r"(a[3]), "r"(b0), "r"(b1));
}

// ---------------------------------------------------------------------------
// K0: condition path.
// ---------------------------------------------------------------------------
__global__ void cond_kernel(const float* __restrict__ cond,
                            const float* __restrict__ W1, const float* __restrict__ b1,
                            const float* __restrict__ W2, const float* __restrict__ b2)
{
    const int b   = blockIdx.x;
    const int tid = threadIdx.x;
    __shared__ float cv[64], h1[64], red[1024];

    if (tid < 64) cv[tid] = cond[b * 64 + tid];
    __syncthreads();
    if (tid < 64) {
        float a = b1[tid];
        #pragma unroll 8
        for (int k = 0; k < 64; k++) a += cv[k] * W1[tid * 64 + k];
        h1[tid] = fmaxf(a, 0.f);
    }
    __syncthreads();
    float a = b2[tid];
    #pragma unroll 8
    for (int k = 0; k < 64; k++) a += h1[k] * W2[tid * 64 + k];
    a = fmaxf(a, 0.f);

    red[tid] = a; __syncthreads();
    for (int o = 512; o > 0; o >>= 1) {
        if (tid < o) red[tid] = fmaxf(red[tid], red[tid + o]);
        __syncthreads();
    }
    const float m = red[0]; __syncthreads();
    const float e = __expf(a - m);
    red[tid] = e; __syncthreads();
    for (int o = 512; o > 0; o >>= 1) {
        if (tid < o) red[tid] += red[tid + o];
        __syncthreads();
    }
    g_Cm[b * HW + tid] = e / red[0];
}

// ---------------------------------------------------------------------------
// prep: split weights into bf16 hi/lo, pack c-pairs.
// ---------------------------------------------------------------------------
__global__ void prep_kernel(const float* __restrict__ Wphi, const float* __restrict__ bphi,
                            const float* __restrict__ Wth,  const float* __restrict__ bth,
                            const float* __restrict__ Wrho, const float* __restrict__ brho)
{
    const int i = blockIdx.x * 256 + threadIdx.x;   // 48 blocks -> 12288
    const int o = i >> 6, cp = i & 63;
    const float* Wsrc = o < 64 ? Wphi : (o < 128 ? Wth : Wrho);
    const int or_ = o & 63;
    const float w0 = Wsrc[(o < 64 ? o : or_ + (o < 128 ? 0 : 0)) * 0 + or_ * 128 + cp * 2];
    const float w1 = Wsrc[or_ * 128 + cp * 2 + 1];
    const __nv_bfloat16 h0 = __float2bfloat16(w0);
    const __nv_bfloat16 h1 = __float2bfloat16(w1);
    const __nv_bfloat16 l0 = __float2bfloat16(w0 - __bfloat162float(h0));
    const __nv_bfloat16 l1 = __float2bfloat16(w1 - __bfloat162float(h1));
    g_Whb[i] = ((uint32_t)__bfloat16_as_ushort(h1) << 16) | __bfloat16_as_ushort(h0);
    g_Wlb[i] = ((uint32_t)__bfloat16_as_ushort(l1) << 16) | __bfloat16_as_ushort(l0);
    if (i < NOUT)
        g_bias[i] = i < 64 ? bphi[i] : (i < 128 ? bth[i - 64] : brho[i - 128]);
}

// ---------------------------------------------------------------------------
// K1: tensor-core projection via mma.sync m16n8k16 bf16, 3-term split.
// D[o=192][s=128] = W[192x128] @ X[128x128].  A=W rows (row-major),
// B=X^T cols (col-major) = Xs[s][c].  Rows padded to 136 bf16 (272B):
// ldmatrix phases read 8 rows x 16B at +16B/row rotation -> conflict-free.
// ---------------------------------------------------------------------------
#define ROWB 272                         // bytes per padded row
#define OFF_XH 0
#define OFF_XL (128 * ROWB)
#define OFF_WH (2 * 128 * ROWB)
#define OFF_WL (2 * 128 * ROWB + 192 * ROWB)
#define OFF_BIAS (2 * 128 * ROWB + 2 * 192 * ROWB)
#define PROJ_SMEM (OFF_BIAS + 192 * 4)

__global__ void __launch_bounds__(256, 1)
proj_mma_kernel(const float* __restrict__ x)
{
    extern __shared__ char sm[];
    const int b = blockIdx.y, tile = blockIdx.x, s0 = tile * 128;
    const int tid = threadIdx.x, wid = tid >> 5, lane = tid & 31;

    // ---- stage weights (bf16 hi/lo, pad 64 -> 68 words per row) ----
    {
        uint32_t* WHs = (uint32_t*)(sm + OFF_WH);
        uint32_t* WLs = (uint32_t*)(sm + OFF_WL);
        for (int i = tid; i < 192 * 64; i += 256) {
            const int o = i >> 6, cp = i & 63;
            WHs[o * 68 + cp] = g_Whb[i];
            WLs[o * 68 + cp] = g_Wlb[i];
        }
        if (tid < NOUT) ((float*)(sm + OFF_BIAS))[tid] = g_bias[tid];
    }
    // ---- stage x: fp32 -> bf16 hi/lo, transposed to [s][c] ----
    {
        uint32_t* XHs = (uint32_t*)(sm + OFF_XH);
        uint32_t* XLs = (uint32_t*)(sm + OFF_XL);
        const float* xb = x + (size_t)b * CIN * S_TOT + s0;
        #pragma unroll 4
        for (int it = 0; it < 32; it++) {
            const int id = it * 256 + tid;           // 8192
            const int s = id & 127, cp = id >> 7;    // cp 0..63
            const float v0 = xb[(size_t)(2 * cp) * S_TOT + s];
            const float v1 = xb[(size_t)(2 * cp + 1) * S_TOT + s];
            const __nv_bfloat16 h0 = __float2bfloat16(v0);
            const __nv_bfloat16 h1 = __float2bfloat16(v1);
            const __nv_bfloat16 l0 = __float2bfloat16(v0 - __bfloat162float(h0));
            const __nv_bfloat16 l1 = __float2bfloat16(v1 - __bfloat162float(h1));
            XHs[s * 68 + cp] = ((uint32_t)__bfloat16_as_ushort(h1) << 16) | __bfloat16_as_ushort(h0);
            XLs[s * 68 + cp] = ((uint32_t)__bfloat16_as_ushort(l1) << 16) | __bfloat16_as_ushort(l0);
        }
    }
    __syncthreads();

    // ---- main MMA loops ----
    const int wo = wid >> 1, ws = wid & 1;
    const int m0 = wo * 48, n0 = ws * 64;
    const uint32_t smb = smem_u32(sm);

    // per-lane ldmatrix byte offsets (within operand buffer, before +kb)
    const uint32_t a_off = (uint32_t)(m0 + (lane & 15)) * ROWB + ((lane >> 4) << 4);
    const uint32_t b_off = (uint32_t)(n0 + (lane & 7))  * ROWB + (((lane >> 3) & 1) << 4);

    float acc[96];
    #pragma unroll
    for (int i = 0; i < 96; i++) acc[i] = 0.f;

    const uint32_t Ab[3] = { OFF_WH, OFF_WL, OFF_WH };
    const uint32_t Bb[3] = { OFF_XH, OFF_XH, OFF_XL };

    #pragma unroll
    for (int t = 0; t < 3; t++) {
        const uint32_t Aaddr = smb + Ab[t] + a_off;
        const uint32_t Baddr = smb + Bb[t] + b_off;
        #pragma unroll
        for (int ks = 0; ks < 8; ks++) {
            const uint32_t kb2 = (uint32_t)ks * 32;   // k-step byte offset
            uint32_t a[3][4];
            #pragma unroll
            for (int mt = 0; mt < 3; mt++)
                LDSM_X4(a[mt], Aaddr + (uint32_t)mt * 16 * ROWB + kb2);
            #pragma unroll
            for (int nt = 0; nt < 8; nt++) {
                uint32_t b0, b1;
                LDSM_X2(b0, b1, Baddr + (uint32_t)nt * 8 * ROWB + kb2);
                #pragma unroll
                for (int mt = 0; mt < 3; mt++)
                    mma_bf16(&acc[(mt * 8 + nt) * 4], a[mt], b0, b1);
            }
        }
    }
    __syncthreads();   // operand smem dead; rsh (alias XH) writable

    // ---- epilogue from fragments ----
    const int g = lane >> 2, tig = lane & 3;
    const float* bias = (const float*)(sm + OFF_BIAS);
    float* rsh = (float*)sm;                    // [64][132] floats, alias XH/XL
    __shared__ float psh[64][2];

    #pragma unroll
    for (int mt = 0; mt < 3; mt++) {
        #pragma unroll
        for (int half = 0; half < 2; half++) {
            const int rbase = m0 + mt * 16 + half * 8;
            const int r = rbase + g;
            const int cat = rbase >> 6;
            const float bv = bias[r];
            if (cat == 0) {
                float* dst = g_A + ((size_t)(b * 64 + r)) * S_TOT + s0 + n0 + 2 * tig;
                #pragma unroll
                for (int nt = 0; nt < 8; nt++) {
                    const float v0 = acc[(mt * 8 + nt) * 4 + half * 2 + 0] + bv;
                    const float v1 = acc[(mt * 8 + nt) * 4 + half * 2 + 1] + bv;
                    *(float2*)(dst + nt * 8) = make_float2(v0, v1);
                }
            } else if (cat == 1) {
                float rs = 0.f;
                float* dst = g_B + ((size_t)(b * 64 + r - 64)) * S_TOT + s0 + n0 + 2 * tig;
                #pragma unroll
                for (int nt = 0; nt < 8; nt++) {
                    const float e0 = __expf(acc[(mt * 8 + nt) * 4 + half * 2 + 0] + bv);
                    const float e1 = __expf(acc[(mt * 8 + nt) * 4 + half * 2 + 1] + bv);
                    *(float2*)(dst + nt * 8) = make_float2(e0, e1);
                    rs += e0 + e1;
                }
                rs += __shfl_xor_sync(0xffffffffu, rs, 1);
                rs += __shfl_xor_sync(0xffffffffu, rs, 2);
                if (tig == 0) psh[r - 64][ws] = rs;
            } else {
                float* dst = rsh + (r - 128) * 132 + n0 + 2 * tig;
                #pragma unroll
                for (int nt = 0; nt < 8; nt++) {
                    const float v0 = acc[(mt * 8 + nt) * 4 + half * 2 + 0] + bv;
                    const float v1 = acc[(mt * 8 + nt) * 4 + half * 2 + 1] + bv;
                    *(float2*)(dst + nt * 8) = make_float2(v0, v1);
                }
            }
        }
    }
    __syncthreads();

    if (tid < 128) {
        // rho channel softmax over 64 rows, one thread per s column
        const int scol = tid;
        float m = -1e30f;
        #pragma unroll 8
        for (int n = 0; n < 64; n++) m = fmaxf(m, rsh[n * 132 + scol]);
        float sum = 0.f;
        #pragma unroll 8
        for (int n = 0; n < 64; n++) {
            const float e = __expf(rsh[n * 132 + scol] - m);
            rsh[n * 132 + scol] = e;
            sum += e;
        }
        const float inv = 1.f / sum;
        #pragma unroll 8
        for (int n = 0; n < 64; n++)
            g_V[((size_t)(b * 64 + n)) * S_TOT + s0 + scol] = rsh[n * 132 + scol] * inv;
    } else if (tid < 192) {
        const int o = tid - 128;
        g_ps[((size_t)(b * 128 + tile)) * 64 + o] = psh[o][0] + psh[o][1];
    }
}

// ---------------------------------------------------------------------------
// K2: reduce tile partial sums -> g_is.
// ---------------------------------------------------------------------------
__global__ void esum_kernel()
{
    const int row  = blockIdx.x * 8 + (threadIdx.x >> 5);
    const int lane = threadIdx.x & 31;
    const int b = row >> 6, n = row & 63;
    const float* p = g_ps + (size_t)b * 128 * 64 + n;
    float s = 0.f;
    #pragma unroll
    for (int t = lane; t < 128; t += 32) s += p[t * 64];
    #pragma unroll
    for (int o = 16; o > 0; o >>= 1) s += __shfl_down_sync(0xffffffffu, s, o);
    if (lane == 0) g_is[row] = 1.f / s;
}

// ---------------------------------------------------------------------------
// K3: attn = transpose(Bm*V), Bm = e*inv.
// ---------------------------------------------------------------------------
__global__ void attn_kernel(float* __restrict__ attn_out)
{
    const int row = blockIdx.x >> 2;
    const int hw0 = (blockIdx.x & 3) * 256;
    const int tid = threadIdx.x;
    const float inv = g_is[row];

    const float4* e4 = (const float4*)(g_B + (size_t)row * S_TOT);
    const float4* v4 = (const float4*)(g_V + (size_t)row * S_TOT);
    __shared__ float sh[256 * 20];

    #pragma unroll
    for (int k = 0; k < 4; k++) {
        const int id = k * 256 + tid;
        const int t  = id >> 6;
        const int f  = id & 63;
        const int si = (t << 10) + hw0 + f * 4;
        const float4 ev = e4[si >> 2];
        const float4 vv = v4[si >> 2];
        float* d = sh + (f * 4) * 20 + t;
        d[0]  = ev.x * vv.x * inv;
        d[20] = ev.y * vv.y * inv;
        d[40] = ev.z * vv.z * inv;
        d[60] = ev.w * vv.w * inv;
    }
    __syncthreads();

    float4* out = (float4*)(attn_out + ((size_t)row * HW + hw0) * T_DIM);
    #pragma unroll
    for (int k = 0; k < 4; k++) {
        const int id = k * 256 + tid;
        out[id] = *(const float4*)(sh + (id >> 2) * 20 + (id & 3) * 4);
    }
}

// ---------------------------------------------------------------------------
// K4: AB_T partials + deterministic reduce.
// ---------------------------------------------------------------------------
__global__ void abt_kernel()
{
    const int b  = blockIdx.y;
    const int ch = blockIdx.x;
    const int sbase = ch * 512;
    const int tid = threadIdx.x;
    const int tm = tid >> 4, tn = tid & 15;

    __shared__ float Ash[64 * 68];
    __shared__ float Bsh[64 * 68];
    __shared__ float invsh[64];
    __shared__ float Csh[HW];

    const float* Abp = g_A + (size_t)b * 64 * S_TOT;
    const float* Bbp = g_B + (size_t)b * 64 * S_TOT;

    if (tid < 64) invsh[tid] = g_is[b * 64 + tid];
    for (int i = tid; i < HW; i += 256) Csh[i] = g_Cm[b * HW + i];

    float acc[16];
    #pragma unroll
    for (int i = 0; i < 16; i++) acc[i] = 0.f;

    for (int st = 0; st < 8; st++) {
        const int s0 = sbase + st * 64;
        __syncthreads();
        for (int idx = tid; idx < 4096; idx += 256) {
            const int scol = idx & 63, r = idx >> 6;
            const int s = s0 + scol;
            Ash[scol * 68 + r] = Abp[(size_t)r * S_TOT + s];
            Bsh[scol * 68 + r] = Bbp[(size_t)r * S_TOT + s] * invsh[r] * Csh[s & (HW - 1)];
        }
        __syncthreads();
        #pragma unroll 4
        for (int ss = 0; ss < 64; ss++) {
            const float4 a = *(const float4*)(Ash + ss * 68 + tm * 4);
            const float4 c = *(const float4*)(Bsh + ss * 68 + tn * 4);
            const float av[4] = {a.x, a.y, a.z, a.w};
            const float cv[4] = {c.x, c.y, c.z, c.w};
            #pragma unroll
            for (int i = 0; i < 4; i++)
                #pragma unroll
                for (int j = 0; j < 4; j++)
                    acc[i * 4 + j] = fmaf(av[i], cv[j], acc[i * 4 + j]);
        }
    }
    float* P = g_Pab + ((size_t)(ch * 8 + b)) * 4096;
    #pragma unroll
    for (int i = 0; i < 4; i++)
        #pragma unroll
        for (int j = 0; j < 4; j++)
            P[(tm * 4 + i) * 64 + tn * 4 + j] = acc[i * 4 + j];
}

__global__ void abred_kernel()
{
    const int o = blockIdx.x * 256 + threadIdx.x;
    float s = 0.f;
    #pragma unroll 8
    for (int c = 0; c < 32; c++) s += g_Pab[(size_t)c * 32768 + o];
    g_AB[o] = s;
}

// ---------------------------------------------------------------------------
// K5: Z = AB @ V.
// ---------------------------------------------------------------------------
__global__ void z_kernel(float* __restrict__ Zout)
{
    const int b  = blockIdx.y;
    const int s0 = blockIdx.x * 128;
    const int tid = threadIdx.x;

    __shared__ float ABsh[64 * 64];
    __shared__ float Vsh [64 * 128];

    for (int idx = tid; idx < 4096; idx += 256)
        ABsh[idx] = g_AB[b * 4096 + idx];
    for (int idx = tid; idx < 64 * 128; idx += 256) {
        const int sc = idx & 127, n = idx >> 7;
        Vsh[n * 128 + sc] = g_V[((size_t)(b * 64 + n)) * S_TOT + s0 + sc];
    }
    __syncthreads();

    const int sc = tid & 127;
    const int mg = tid >> 7;

    float acc[32];
    #pragma unroll
    for (int i = 0; i < 32; i++) acc[i] = 0.f;

    for (int n0 = 0; n0 < 64; n0 += 4) {
        const float v0 = Vsh[(n0 + 0) * 128 + sc];
        const float v1 = Vsh[(n0 + 1) * 128 + sc];
        const float v2 = Vsh[(n0 + 2) * 128 + sc];
        const float v3 = Vsh[(n0 + 3) * 128 + sc];
        #pragma unroll
        for (int k = 0; k < 32; k++) {
            const float4 ab = *(const float4*)(ABsh + (mg * 32 + k) * 64 + n0);
            acc[k] = fmaf(ab.x, v0, acc[k]);
            acc[k] = fmaf(ab.y, v1, acc[k]);
            acc[k] = fmaf(ab.z, v2, acc[k]);
            acc[k] = fmaf(ab.w, v3, acc[k]);
        }
    }
    float* Z = Zout + ((size_t)(b * 64 + mg * 32)) * S_TOT + s0 + sc;
    #pragma unroll
    for (int i = 0; i < 32; i++) Z[(size_t)i * S_TOT] = acc[i];
}

// ---------------------------------------------------------------------------
extern "C" void kernel_launch(void* const* d_in, const int* in_sizes, int n_in,
                              void* d_out, int out_size)
{
    (void)in_sizes; (void)n_in; (void)out_size;
    const float* input = (const float*)d_in[0];
    const float* cond  = (const float*)d_in[1];
    const float* Wphi  = (const float*)d_in[2];
    const float* bphi  = (const float*)d_in[3];
    const float* Wth   = (const float*)d_in[4];
    const float* bth   = (const float*)d_in[5];
    const float* Wrho  = (const float*)d_in[6];
    const float* brho  = (const float*)d_in[7];
    const float* W1    = (const float*)d_in[8];
    const float* b1    = (const float*)d_in[9];
    const float* W2    = (const float*)d_in[10];
    const float* b2    = (const float*)d_in[11];

    float* Z    = (float*)d_out;
    float* attn = Z + (size_t)BATCH * 64 * S_TOT;

    cudaFuncSetAttribute(proj_mma_kernel,
                         cudaFuncAttributeMaxDynamicSharedMemorySize, PROJ_SMEM);

    cond_kernel<<<BATCH, 1024>>>(cond, W1, b1, W2, b2);
    prep_kernel<<<48, 256>>>(Wphi, bphi, Wth, bth, Wrho, brho);
    proj_mma_kernel<<<dim3(128, BATCH), 256, PROJ_SMEM>>>(input);
    esum_kernel<<<64, 256>>>();
    attn_kernel<<<512 * 4, 256>>>(attn);
    abt_kernel<<<dim3(32, BATCH), 256>>>();
    abred_kernel<<<128, 256>>>();
    z_kernel<<<dim3(128, BATCH), 256>>>(Z);
}

// round 6
// speedup vs baseline: 1.9029x; 1.0599x over previous
#include <cuda_runtime.h>
#include <cuda_bf16.h>
#include <cstdint>

// ---------------------------------------------------------------------------
//   B=8, C=128, T=16, H=32, W=32  -> S = 16384, HW = 1024
//   M = N = 64, CS = 64.  Output: Z (8,64,16,32,32) ++ attn (8,64,32,32,16).
// ---------------------------------------------------------------------------
#define BATCH 8
#define CIN   128
#define S_TOT 16384
#define HW    1024
#define T_DIM 16
#define NOUT  192

// -------------------------- device scratch --------------------------------
__device__ float g_A [BATCH * 64 * S_TOT];        // phi (fp32)
__device__ float g_B [BATCH * 64 * S_TOT];        // exp(theta logits)
__device__ float g_V [BATCH * 64 * S_TOT];        // rho softmax (fp32, for attn)
__device__ uint32_t g_Vt[BATCH * S_TOT * 64];     // V transposed, packed bf16 hi|lo
__device__ float g_Cm[BATCH * HW];
__device__ float g_ps[BATCH * 128 * 64];
__device__ float g_is[BATCH * 64];
__device__ float g_Pab[32 * BATCH * 64 * 64];
__device__ float g_AB [BATCH * 64 * 64];
// weights pre-split to bf16 hi/lo, packed pairs of c
__device__ uint32_t g_Whb[NOUT * 64];
__device__ uint32_t g_Wlb[NOUT * 64];
__device__ float    g_bias[NOUT];

// ------------------------------ helpers -----------------------------------
__device__ __forceinline__ uint32_t smem_u32(const void* p) {
    uint32_t a;
    asm("{ .reg .u64 t; cvta.to.shared.u64 t, %1; cvt.u32.u64 %0, t; }"
        : "=r"(a) : "l"(p));
    return a;
}

#define LDSM_X4(r, addr) \
    asm volatile("ldmatrix.sync.aligned.m8n8.x4.shared.b16 {%0,%1,%2,%3}, [%4];" \
        : "=r"((r)[0]), "=r"((r)[1]), "=r"((r)[2]), "=r"((r)[3]) : "r"(addr))
#define LDSM_X2(r0, r1, addr) \
    asm volatile("ldmatrix.sync.aligned.m8n8.x2.shared.b16 {%0,%1}, [%2];" \
        : "=r"(r0), "=r"(r1) : "r"(addr))

__device__ __forceinline__ void mma_bf16(float* c, const uint32_t* a,
                                         uint32_t b0, uint32_t b1) {
    asm volatile(
        "mma.sync.aligned.m16n8k16.row.col.f32.bf16.bf16.f32 "
        "{%0,%1,%2,%3}, {%4,%5,%6,%7}, {%8,%9}, {%0,%1,%2,%3};"
        : "+f"(c[0]), "+f"(c[1]), "+f"(c[2]), "+f"(c[3])
        : "r"(a[0]), "r"(a[1]), "r"(a[2]), "r"(a[3]), "r"(b0), "r"(b1));
}

__device__ __forceinline__ void bf16_split(float v, uint16_t& h, uint16_t& l) {
    const __nv_bfloat16 hh = __float2bfloat16(v);
    const __nv_bfloat16 ll = __float2bfloat16(v - __bfloat162float(hh));
    h = __bfloat16_as_ushort(hh);
    l = __bfloat16_as_ushort(ll);
}

// ---------------------------------------------------------------------------
// K0: condition path.
// ---------------------------------------------------------------------------
__global__ void cond_kernel(const float* __restrict__ cond,
                            const float* __restrict__ W1, const float* __restrict__ b1,
                            const float* __restrict__ W2, const float* __restrict__ b2)
{
    const int b   = blockIdx.x;
    const int tid = threadIdx.x;
    __shared__ float cv[64], h1[64], red[1024];

    if (tid < 64) cv[tid] = cond[b * 64 + tid];
    __syncthreads();
    if (tid < 64) {
        float a = b1[tid];
        #pragma unroll 8
        for (int k = 0; k < 64; k++) a += cv[k] * W1[tid * 64 + k];
        h1[tid] = fmaxf(a, 0.f);
    }
    __syncthreads();
    float a = b2[tid];
    #pragma unroll 8
    for (int k = 0; k < 64; k++) a += h1[k] * W2[tid * 64 + k];
    a = fmaxf(a, 0.f);

    red[tid] = a; __syncthreads();
    for (int o = 512; o > 0; o >>= 1) {
        if (tid < o) red[tid] = fmaxf(red[tid], red[tid + o]);
        __syncthreads();
    }
    const float m = red[0]; __syncthreads();
    const float e = __expf(a - m);
    red[tid] = e; __syncthreads();
    for (int o = 512; o > 0; o >>= 1) {
        if (tid < o) red[tid] += red[tid + o];
        __syncthreads();
    }
    g_Cm[b * HW + tid] = e / red[0];
}

// ---------------------------------------------------------------------------
// prep: split weights into bf16 hi/lo, pack c-pairs.
// ---------------------------------------------------------------------------
__global__ void prep_kernel(const float* __restrict__ Wphi, const float* __restrict__ bphi,
                            const float* __restrict__ Wth,  const float* __restrict__ bth,
                            const float* __restrict__ Wrho, const float* __restrict__ brho)
{
    const int i = blockIdx.x * 256 + threadIdx.x;   // 48 blocks -> 12288
    const int o = i >> 6, cp = i & 63;
    const float* Wsrc = o < 64 ? Wphi : (o < 128 ? Wth : Wrho);
    const int or_ = o & 63;
    const float w0 = Wsrc[or_ * 128 + cp * 2];
    const float w1 = Wsrc[or_ * 128 + cp * 2 + 1];
    uint16_t h0, l0, h1, l1;
    bf16_split(w0, h0, l0);
    bf16_split(w1, h1, l1);
    g_Whb[i] = ((uint32_t)h1 << 16) | h0;
    g_Wlb[i] = ((uint32_t)l1 << 16) | l0;
    if (i < NOUT)
        g_bias[i] = i < 64 ? bphi[i] : (i < 128 ? bth[i - 64] : brho[i - 128]);
}

// ---------------------------------------------------------------------------
// K1: tensor-core projection (proven R5 kernel) + NEW g_Vt packed writes.
// ---------------------------------------------------------------------------
#define ROWB 272
#define OFF_XH 0
#define OFF_XL (128 * ROWB)
#define OFF_WH (2 * 128 * ROWB)
#define OFF_WL (2 * 128 * ROWB + 192 * ROWB)
#define OFF_BIAS (2 * 128 * ROWB + 2 * 192 * ROWB)
#define PROJ_SMEM (OFF_BIAS + 192 * 4)

__global__ void __launch_bounds__(256, 1)
proj_mma_kernel(const float* __restrict__ x)
{
    extern __shared__ char sm[];
    const int b = blockIdx.y, tile = blockIdx.x, s0 = tile * 128;
    const int tid = threadIdx.x, wid = tid >> 5, lane = tid & 31;

    {
        uint32_t* WHs = (uint32_t*)(sm + OFF_WH);
        uint32_t* WLs = (uint32_t*)(sm + OFF_WL);
        for (int i = tid; i < 192 * 64; i += 256) {
            const int o = i >> 6, cp = i & 63;
            WHs[o * 68 + cp] = g_Whb[i];
            WLs[o * 68 + cp] = g_Wlb[i];
        }
        if (tid < NOUT) ((float*)(sm + OFF_BIAS))[tid] = g_bias[tid];
    }
    {
        uint32_t* XHs = (uint32_t*)(sm + OFF_XH);
        uint32_t* XLs = (uint32_t*)(sm + OFF_XL);
        const float* xb = x + (size_t)b * CIN * S_TOT + s0;
        #pragma unroll 4
        for (int it = 0; it < 32; it++) {
            const int id = it * 256 + tid;
            const int s = id & 127, cp = id >> 7;
            const float v0 = xb[(size_t)(2 * cp) * S_TOT + s];
            const float v1 = xb[(size_t)(2 * cp + 1) * S_TOT + s];
            uint16_t h0, l0, h1, l1;
            bf16_split(v0, h0, l0);
            bf16_split(v1, h1, l1);
            XHs[s * 68 + cp] = ((uint32_t)h1 << 16) | h0;
            XLs[s * 68 + cp] = ((uint32_t)l1 << 16) | l0;
        }
    }
    __syncthreads();

    const int wo = wid >> 1, ws = wid & 1;
    const int m0 = wo * 48, n0 = ws * 64;
    const uint32_t smb = smem_u32(sm);

    const uint32_t a_off = (uint32_t)(m0 + (lane & 15)) * ROWB + ((lane >> 4) << 4);
    const uint32_t b_off = (uint32_t)(n0 + (lane & 7))  * ROWB + (((lane >> 3) & 1) << 4);

    float acc[96];
    #pragma unroll
    for (int i = 0; i < 96; i++) acc[i] = 0.f;

    const uint32_t Ab[3] = { OFF_WH, OFF_WL, OFF_WH };
    const uint32_t Bb[3] = { OFF_XH, OFF_XH, OFF_XL };

    #pragma unroll
    for (int t = 0; t < 3; t++) {
        const uint32_t Aaddr = smb + Ab[t] + a_off;
        const uint32_t Baddr = smb + Bb[t] + b_off;
        #pragma unroll
        for (int ks = 0; ks < 8; ks++) {
            const uint32_t kb2 = (uint32_t)ks * 32;
            uint32_t a[3][4];
            #pragma unroll
            for (int mt = 0; mt < 3; mt++)
                LDSM_X4(a[mt], Aaddr + (uint32_t)mt * 16 * ROWB + kb2);
            #pragma unroll
            for (int nt = 0; nt < 8; nt++) {
                uint32_t b0, b1;
                LDSM_X2(b0, b1, Baddr + (uint32_t)nt * 8 * ROWB + kb2);
                #pragma unroll
                for (int mt = 0; mt < 3; mt++)
                    mma_bf16(&acc[(mt * 8 + nt) * 4], a[mt], b0, b1);
            }
        }
    }
    __syncthreads();

    const int g = lane >> 2, tig = lane & 3;
    const float* bias = (const float*)(sm + OFF_BIAS);
    float* rsh = (float*)sm;                    // [64][132], alias XH/XL
    __shared__ float psh[64][2];

    #pragma unroll
    for (int mt = 0; mt < 3; mt++) {
        #pragma unroll
        for (int half = 0; half < 2; half++) {
            const int rbase = m0 + mt * 16 + half * 8;
            const int r = rbase + g;
            const int cat = rbase >> 6;
            const float bv = bias[r];
            if (cat == 0) {
                float* dst = g_A + ((size_t)(b * 64 + r)) * S_TOT + s0 + n0 + 2 * tig;
                #pragma unroll
                for (int nt = 0; nt < 8; nt++) {
                    const float v0 = acc[(mt * 8 + nt) * 4 + half * 2 + 0] + bv;
                    const float v1 = acc[(mt * 8 + nt) * 4 + half * 2 + 1] + bv;
                    *(float2*)(dst + nt * 8) = make_float2(v0, v1);
                }
            } else if (cat == 1) {
                float rs = 0.f;
                float* dst = g_B + ((size_t)(b * 64 + r - 64)) * S_TOT + s0 + n0 + 2 * tig;
                #pragma unroll
                for (int nt = 0; nt < 8; nt++) {
                    const float e0 = __expf(acc[(mt * 8 + nt) * 4 + half * 2 + 0] + bv);
                    const float e1 = __expf(acc[(mt * 8 + nt) * 4 + half * 2 + 1] + bv);
                    *(float2*)(dst + nt * 8) = make_float2(e0, e1);
                    rs += e0 + e1;
                }
                rs += __shfl_xor_sync(0xffffffffu, rs, 1);
                rs += __shfl_xor_sync(0xffffffffu, rs, 2);
                if (tig == 0) psh[r - 64][ws] = rs;
            } else {
                float* dst = rsh + (r - 128) * 132 + n0 + 2 * tig;
                #pragma unroll
                for (int nt = 0; nt < 8; nt++) {
                    const float v0 = acc[(mt * 8 + nt) * 4 + half * 2 + 0] + bv;
                    const float v1 = acc[(mt * 8 + nt) * 4 + half * 2 + 1] + bv;
                    *(float2*)(dst + nt * 8) = make_float2(v0, v1);
                }
            }
        }
    }
    __syncthreads();

    if (tid < 128) {
        const int scol = tid;
        float m = -1e30f;
        #pragma unroll 8
        for (int n = 0; n < 64; n++) m = fmaxf(m, rsh[n * 132 + scol]);
        float sum = 0.f;
        #pragma unroll 8
        for (int n = 0; n < 64; n++) {
            const float e = __expf(rsh[n * 132 + scol] - m);
            rsh[n * 132 + scol] = e;
            sum += e;
        }
        const float inv = 1.f / sum;
        uint32_t* vt = g_Vt + ((size_t)b * S_TOT + s0 + scol) * 64;
        #pragma unroll 8
        for (int n = 0; n < 64; n++) {
            const float v = rsh[n * 132 + scol] * inv;
            g_V[((size_t)(b * 64 + n)) * S_TOT + s0 + scol] = v;
            uint16_t h, l;
            bf16_split(v, h, l);
            vt[n] = ((uint32_t)l << 16) | h;
        }
    } else if (tid < 192) {
        const int o = tid - 128;
        g_ps[((size_t)(b * 128 + tile)) * 64 + o] = psh[o][0] + psh[o][1];
    }
}

// ---------------------------------------------------------------------------
// K2: reduce tile partial sums -> g_is.
// ---------------------------------------------------------------------------
__global__ void esum_kernel()
{
    const int row  = blockIdx.x * 8 + (threadIdx.x >> 5);
    const int lane = threadIdx.x & 31;
    const int b = row >> 6, n = row & 63;
    const float* p = g_ps + (size_t)b * 128 * 64 + n;
    float s = 0.f;
    #pragma unroll
    for (int t = lane; t < 128; t += 32) s += p[t * 64];
    #pragma unroll
    for (int o = 16; o > 0; o >>= 1) s += __shfl_down_sync(0xffffffffu, s, o);
    if (lane == 0) g_is[row] = 1.f / s;
}

// ---------------------------------------------------------------------------
// K3: attn = transpose(Bm*V), Bm = e*inv.
// ---------------------------------------------------------------------------
__global__ void attn_kernel(float* __restrict__ attn_out)
{
    const int row = blockIdx.x >> 2;
    const int hw0 = (blockIdx.x & 3) * 256;
    const int tid = threadIdx.x;
    const float inv = g_is[row];

    const float4* e4 = (const float4*)(g_B + (size_t)row * S_TOT);
    const float4* v4 = (const float4*)(g_V + (size_t)row * S_TOT);
    __shared__ float sh[256 * 20];

    #pragma unroll
    for (int k = 0; k < 4; k++) {
        const int id = k * 256 + tid;
        const int t  = id >> 6;
        const int f  = id & 63;
        const int si = (t << 10) + hw0 + f * 4;
        const float4 ev = e4[si >> 2];
        const float4 vv = v4[si >> 2];
        float* d = sh + (f * 4) * 20 + t;
        d[0]  = ev.x * vv.x * inv;
        d[20] = ev.y * vv.y * inv;
        d[40] = ev.z * vv.z * inv;
        d[60] = ev.w * vv.w * inv;
    }
    __syncthreads();

    float4* out = (float4*)(attn_out + ((size_t)row * HW + hw0) * T_DIM);
    #pragma unroll
    for (int k = 0; k < 4; k++) {
        const int id = k * 256 + tid;
        out[id] = *(const float4*)(sh + (id >> 2) * 20 + (id & 3) * 4);
    }
}

// ---------------------------------------------------------------------------
// K4: AB_T partials via HMMA. grid (32 chunks, 8 b), 256 threads.
// Per 64-s k-tile: stage A (split) and BC = e*inv*Cm (split), 3-term mma.
// Pitch 72 bf16 (144 B) -> 16B/row rotation, conflict-free ldmatrix.
// ---------------------------------------------------------------------------
__global__ void __launch_bounds__(256)
abt_kernel()
{
    const int b  = blockIdx.y;
    const int ch = blockIdx.x;
    const int tid = threadIdx.x, wid = tid >> 5, lane = tid & 31;

    __shared__ uint16_t sAh[64 * 72], sAl[64 * 72];
    __shared__ uint16_t sBh[64 * 72], sBl[64 * 72];
    __shared__ float invsh[64];
    __shared__ float Csh[HW];

    if (tid < 64) invsh[tid] = g_is[b * 64 + tid];
    for (int i = tid; i < HW; i += 256) Csh[i] = g_Cm[b * HW + i];

    const float* Abp = g_A + (size_t)b * 64 * S_TOT;
    const float* Bbp = g_B + (size_t)b * 64 * S_TOT;

    const int wo = wid >> 1, ws = wid & 1;
    const int m0 = wo * 16, n0 = ws * 32;
    const uint32_t sAhB = smem_u32(sAh), sAlB = smem_u32(sAl);
    const uint32_t sBhB = smem_u32(sBh), sBlB = smem_u32(sBl);
    const uint32_t a_off = (uint32_t)(m0 + (lane & 15)) * 144 + ((lane >> 4) << 4);
    const uint32_t b_off = (uint32_t)(n0 + (lane & 7))  * 144 + (((lane >> 3) & 1) << 4);

    float acc[16];
    #pragma unroll
    for (int i = 0; i < 16; i++) acc[i] = 0.f;

    for (int st = 0; st < 8; st++) {
        const int s0 = ch * 512 + st * 64;
        __syncthreads();
        for (int idx = tid; idx < 4096; idx += 256) {
            const int r = idx >> 6, sc = idx & 63;
            const int s = s0 + sc;
            uint16_t h, l;
            bf16_split(Abp[(size_t)r * S_TOT + s], h, l);
            sAh[r * 72 + sc] = h; sAl[r * 72 + sc] = l;
            const float ev = Bbp[(size_t)r * S_TOT + s] * invsh[r] * Csh[s & (HW - 1)];
            bf16_split(ev, h, l);
            sBh[r * 72 + sc] = h; sBl[r * 72 + sc] = l;
        }
        __syncthreads();

        #pragma unroll
        for (int t = 0; t < 3; t++) {
            const uint32_t Aaddr = (t == 1 ? sAlB : sAhB) + a_off;
            const uint32_t Baddr = (t == 2 ? sBlB : sBhB) + b_off;
            #pragma unroll
            for (int ks = 0; ks < 4; ks++) {
                uint32_t a[4];
                LDSM_X4(a, Aaddr + (uint32_t)ks * 32);
                #pragma unroll
                for (int nt = 0; nt < 4; nt++) {
                    uint32_t b0, b1;
                    LDSM_X2(b0, b1, Baddr + (uint32_t)nt * 8 * 144 + (uint32_t)ks * 32);
                    mma_bf16(&acc[nt * 4], a, b0, b1);
                }
            }
        }
    }

    const int g = lane >> 2, tig = lane & 3;
    float* P = g_Pab + ((size_t)(ch * 8 + b)) * 4096;
    #pragma unroll
    for (int nt = 0; nt < 4; nt++)
        #pragma unroll
        for (int half = 0; half < 2; half++) {
            const int row = m0 + half * 8 + g;
            const int col = n0 + nt * 8 + 2 * tig;
            *(float2*)(P + row * 64 + col) =
                make_float2(acc[nt * 4 + half * 2], acc[nt * 4 + half * 2 + 1]);
        }
}

__global__ void abred_kernel()
{
    const int o = blockIdx.x * 256 + threadIdx.x;
    float s = 0.f;
    #pragma unroll 8
    for (int c = 0; c < 32; c++) s += g_Pab[(size_t)c * 32768 + o];
    g_AB[o] = s;
}

// ---------------------------------------------------------------------------
// K5: Z = AB @ V via HMMA.  grid (128 s-tiles, 8 b), 256 threads.
// B operand from g_Vt [s][ch] packed bf16 (no transpose needed).
// ---------------------------------------------------------------------------
#define Z_SAB  (64 * 72)
#define Z_SV   (128 * 72)
#define Z_SMEM ((2 * Z_SAB + 2 * Z_SV) * 2)

__global__ void __launch_bounds__(256)
z_kernel(float* __restrict__ Zout)
{
    extern __shared__ uint16_t zsm[];
    uint16_t* sABh = zsm;
    uint16_t* sABl = zsm + Z_SAB;
    uint16_t* sVh  = zsm + 2 * Z_SAB;
    uint16_t* sVl  = zsm + 2 * Z_SAB + Z_SV;

    const int b  = blockIdx.y;
    const int s0 = blockIdx.x * 128;
    const int tid = threadIdx.x, wid = tid >> 5, lane = tid & 31;

    for (int idx = tid; idx < 4096; idx += 256) {
        const int r = idx >> 6, k = idx & 63;
        uint16_t h, l;
        bf16_split(g_AB[b * 4096 + idx], h, l);
        sABh[r * 72 + k] = h; sABl[r * 72 + k] = l;
    }
    {
        const uint32_t* vt = g_Vt + ((size_t)b * S_TOT + s0) * 64;
        #pragma unroll 4
        for (int it = 0; it < 32; it++) {
            const int idx = it * 256 + tid;          // 8192
            const int srow = idx >> 6, c = idx & 63;
            const uint32_t p = vt[srow * 64 + c];
            sVh[srow * 72 + c] = (uint16_t)p;
            sVl[srow * 72 + c] = (uint16_t)(p >> 16);
        }
    }
    __syncthreads();

    const int wm = wid >> 2, wn = wid & 3;
    const int m0 = wm * 32, n0 = wn * 32;
    const uint32_t sABhB = smem_u32(sABh), sABlB = smem_u32(sABl);
    const uint32_t sVhB  = smem_u32(sVh),  sVlB  = smem_u32(sVl);
    const uint32_t a_off = (uint32_t)(m0 + (lane & 15)) * 144 + ((lane >> 4) << 4);
    const uint32_t b_off = (uint32_t)(n0 + (lane & 7))  * 144 + (((lane >> 3) & 1) << 4);

    float acc[32];
    #pragma unroll
    for (int i = 0; i < 32; i++) acc[i] = 0.f;

    #pragma unroll
    for (int t = 0; t < 3; t++) {
        const uint32_t Aaddr = (t == 1 ? sABlB : sABhB) + a_off;
        const uint32_t Baddr = (t == 2 ? sVlB  : sVhB)  + b_off;
        #pragma unroll
        for (int ks = 0; ks < 4; ks++) {
            uint32_t a0[4], a1[4];
            LDSM_X4(a0, Aaddr + (uint32_t)ks * 32);
            LDSM_X4(a1, Aaddr + 16 * 144 + (uint32_t)ks * 32);
            #pragma unroll
            for (int nt = 0; nt < 4; nt++) {
                uint32_t b0, b1;
                LDSM_X2(b0, b1, Baddr + (uint32_t)nt * 8 * 144 + (uint32_t)ks * 32);
                mma_bf16(&acc[nt * 4], a0, b0, b1);
                mma_bf16(&acc[16 + nt * 4], a1, b0, b1);
            }
        }
    }

    const int g = lane >> 2, tig = lane & 3;
    #pragma unroll
    for (int mt = 0; mt < 2; mt++)
        #pragma unroll
        for (int nt = 0; nt < 4; nt++)
            #pragma unroll
            for (int half = 0; half < 2; half++) {
                const int row = m0 + mt * 16 + half * 8 + g;
                const int col = s0 + n0 + nt * 8 + 2 * tig;
                *(float2*)(Zout + ((size_t)(b * 64 + row)) * S_TOT + col) =
                    make_float2(acc[mt * 16 + nt * 4 + half * 2],
                                acc[mt * 16 + nt * 4 + half * 2 + 1]);
            }
}

// ---------------------------------------------------------------------------
extern "C" void kernel_launch(void* const* d_in, const int* in_sizes, int n_in,
                              void* d_out, int out_size)
{
    (void)in_sizes; (void)n_in; (void)out_size;
    const float* input = (const float*)d_in[0];
    const float* cond  = (const float*)d_in[1];
    const float* Wphi  = (const float*)d_in[2];
    const float* bphi  = (const float*)d_in[3];
    const float* Wth   = (const float*)d_in[4];
    const float* bth   = (const float*)d_in[5];
    const float* Wrho  = (const float*)d_in[6];
    const float* brho  = (const float*)d_in[7];
    const float* W1    = (const float*)d_in[8];
    const float* b1    = (const float*)d_in[9];
    const float* W2    = (const float*)d_in[10];
    const float* b2    = (const float*)d_in[11];

    float* Z    = (float*)d_out;
    float* attn = Z + (size_t)BATCH * 64 * S_TOT;

    cudaFuncSetAttribute(proj_mma_kernel,
                         cudaFuncAttributeMaxDynamicSharedMemorySize, PROJ_SMEM);
    cudaFuncSetAttribute(z_kernel,
                         cudaFuncAttributeMaxDynamicSharedMemorySize, Z_SMEM);

    cond_kernel<<<BATCH, 1024>>>(cond, W1, b1, W2, b2);
    prep_kernel<<<48, 256>>>(Wphi, bphi, Wth, bth, Wrho, brho);
    proj_mma_kernel<<<dim3(128, BATCH), 256, PROJ_SMEM>>>(input);
    esum_kernel<<<64, 256>>>();
    attn_kernel<<<512 * 4, 256>>>(attn);
    abt_kernel<<<dim3(32, BATCH), 256>>>();
    abred_kernel<<<128, 256>>>();
    z_kernel<<<dim3(128, BATCH), 256, Z_SMEM>>>(Z);
}

// round 7
// speedup vs baseline: 1.9313x; 1.0149x over previous
#include <cuda_runtime.h>
#include <cuda_bf16.h>
#include <cstdint>

// ---------------------------------------------------------------------------
//   B=8, C=128, T=16, H=32, W=32  -> S = 16384, HW = 1024
//   M = N = 64, CS = 64.  Output: Z (8,64,16,32,32) ++ attn (8,64,32,32,16).
// ---------------------------------------------------------------------------
#define BATCH 8
#define CIN   128
#define S_TOT 16384
#define HW    1024
#define T_DIM 16
#define NOUT  192

// -------------------------- device scratch --------------------------------
__device__ float g_B [BATCH * 64 * S_TOT];        // exp(theta logits)
__device__ float g_V [BATCH * 64 * S_TOT];        // rho softmax (fp32, for attn)
__device__ uint32_t g_Vt[BATCH * S_TOT * 64];     // V transposed, packed bf16 hi|lo
__device__ float g_Cm[BATCH * HW];
__device__ float g_ps[BATCH * 128 * 64];          // per-tile theta exp sums
__device__ float g_Pab[BATCH * 128 * 64 * 64];    // AB_T per-tile partials (16MB)
__device__ float g_AB [BATCH * 64 * 64];
// weights pre-split to bf16 hi/lo, packed pairs of c
__device__ uint32_t g_Whb[NOUT * 64];
__device__ uint32_t g_Wlb[NOUT * 64];
__device__ float    g_bias[NOUT];

// ------------------------------ helpers -----------------------------------
__device__ __forceinline__ uint32_t smem_u32(const void* p) {
    uint32_t a;
    asm("{ .reg .u64 t; cvta.to.shared.u64 t, %1; cvt.u32.u64 %0, t; }"
        : "=r"(a) : "l"(p));
    return a;
}

#define LDSM_X4(r, addr) \
    asm volatile("ldmatrix.sync.aligned.m8n8.x4.shared.b16 {%0,%1,%2,%3}, [%4];" \
        : "=r"((r)[0]), "=r"((r)[1]), "=r"((r)[2]), "=r"((r)[3]) : "r"(addr))
#define LDSM_X2(r0, r1, addr) \
    asm volatile("ldmatrix.sync.aligned.m8n8.x2.shared.b16 {%0,%1}, [%2];" \
        : "=r"(r0), "=r"(r1) : "r"(addr))

__device__ __forceinline__ void mma_bf16(float* c, const uint32_t* a,
                                         uint32_t b0, uint32_t b1) {
    asm volatile(
        "mma.sync.aligned.m16n8k16.row.col.f32.bf16.bf16.f32 "
        "{%0,%1,%2,%3}, {%4,%5,%6,%7}, {%8,%9}, {%0,%1,%2,%3};"
        : "+f"(c[0]), "+f"(c[1]), "+f"(c[2]), "+f"(c[3])
        : "r"(a[0]), "r"(a[1]), "r"(a[2]), "r"(a[3]), "r"(b0), "r"(b1));
}

__device__ __forceinline__ void bf16_split(float v, uint16_t& h, uint16_t& l) {
    const __nv_bfloat16 hh = __float2bfloat16(v);
    const __nv_bfloat16 ll = __float2bfloat16(v - __bfloat162float(hh));
    h = __bfloat16_as_ushort(hh);
    l = __bfloat16_as_ushort(ll);
}
__device__ __forceinline__ uint32_t pack_split_hi(float v0, float v1) {
    uint16_t h0, l0, h1, l1;
    bf16_split(v0, h0, l0); bf16_split(v1, h1, l1);
    return ((uint32_t)h1 << 16) | h0;
}

// ---------------------------------------------------------------------------
// K0: condition path.
// ---------------------------------------------------------------------------
__global__ void cond_kernel(const float* __restrict__ cond,
                            const float* __restrict__ W1, const float* __restrict__ b1,
                            const float* __restrict__ W2, const float* __restrict__ b2)
{
    const int b   = blockIdx.x;
    const int tid = threadIdx.x;
    __shared__ float cv[64], h1[64], red[1024];

    if (tid < 64) cv[tid] = cond[b * 64 + tid];
    __syncthreads();
    if (tid < 64) {
        float a = b1[tid];
        #pragma unroll 8
        for (int k = 0; k < 64; k++) a += cv[k] * W1[tid * 64 + k];
        h1[tid] = fmaxf(a, 0.f);
    }
    __syncthreads();
    float a = b2[tid];
    #pragma unroll 8
    for (int k = 0; k < 64; k++) a += h1[k] * W2[tid * 64 + k];
    a = fmaxf(a, 0.f);

    red[tid] = a; __syncthreads();
    for (int o = 512; o > 0; o >>= 1) {
        if (tid < o) red[tid] = fmaxf(red[tid], red[tid + o]);
        __syncthreads();
    }
    const float m = red[0]; __syncthreads();
    const float e = __expf(a - m);
    red[tid] = e; __syncthreads();
    for (int o = 512; o > 0; o >>= 1) {
        if (tid < o) red[tid] += red[tid + o];
        __syncthreads();
    }
    g_Cm[b * HW + tid] = e / red[0];
}

// ---------------------------------------------------------------------------
// prep (split into 2 launches so proj is the 4th launch -> gets profiled):
// split weights into bf16 hi/lo, pack c-pairs.
// ---------------------------------------------------------------------------
__device__ __forceinline__ void prep_one(int i, const float* Wphi, const float* Wth,
                                         const float* Wrho)
{
    const int o = i >> 6, cp = i & 63;
    const float* Wsrc = o < 64 ? Wphi : (o < 128 ? Wth : Wrho);
    const int or_ = o & 63;
    const float w0 = Wsrc[or_ * 128 + cp * 2];
    const float w1 = Wsrc[or_ * 128 + cp * 2 + 1];
    uint16_t h0, l0, h1, l1;
    bf16_split(w0, h0, l0);
    bf16_split(w1, h1, l1);
    g_Whb[i] = ((uint32_t)h1 << 16) | h0;
    g_Wlb[i] = ((uint32_t)l1 << 16) | l0;
}

__global__ void prepA_kernel(const float* __restrict__ Wphi,
                             const float* __restrict__ Wth,
                             const float* __restrict__ Wrho)
{
    const int i = blockIdx.x * 256 + threadIdx.x;   // 24 blocks: o 0..95
    prep_one(i, Wphi, Wth, Wrho);
}

__global__ void prepB_kernel(const float* __restrict__ Wphi, const float* __restrict__ bphi,
                             const float* __restrict__ Wth,  const float* __restrict__ bth,
                             const float* __restrict__ Wrho, const float* __restrict__ brho)
{
    const int i = blockIdx.x * 256 + threadIdx.x;   // 24 blocks: o 96..191
    prep_one(6144 + i, Wphi, Wth, Wrho);
    if (i < NOUT)
        g_bias[i] = i < 64 ? bphi[i] : (i < 128 ? bth[i - 64] : brho[i - 128]);
}

// ---------------------------------------------------------------------------
// K1: tensor-core projection + fused per-tile AB_T partial.
//   main:  D[o=192][s=128] = W @ X (3-term bf16 split)
//   fused: P[m=64][n=64]  = A_tile @ (e*Cm)_tile^T  (3-term bf16 split)
// ---------------------------------------------------------------------------
#define ROWB 272
#define OFF_XH 0
#define OFF_XL (128 * ROWB)
#define OFF_WH (2 * 128 * ROWB)
#define OFF_WL (2 * 128 * ROWB + 192 * ROWB)
#define OFF_BIAS (2 * 128 * ROWB + 2 * 192 * ROWB)
#define PROJ_SMEM (OFF_BIAS + 192 * 4)
// second-MMA operand region (aliases WH/WL, dead after main loop)
#define OFF2_AH (OFF_WH)
#define OFF2_AL (OFF_WH + 64 * ROWB)
#define OFF2_EH (OFF_WH + 2 * 64 * ROWB)
#define OFF2_EL (OFF_WH + 3 * 64 * ROWB)

__global__ void __launch_bounds__(256, 1)
proj_mma_kernel(const float* __restrict__ x)
{
    extern __shared__ char sm[];
    const int b = blockIdx.y, tile = blockIdx.x, s0 = tile * 128;
    const int tid = threadIdx.x, wid = tid >> 5, lane = tid & 31;

    __shared__ float psh[64][2];
    __shared__ float Csh[128];

    if (tid < 128) Csh[tid] = g_Cm[b * HW + ((s0 + tid) & (HW - 1))];

    {
        uint32_t* WHs = (uint32_t*)(sm + OFF_WH);
        uint32_t* WLs = (uint32_t*)(sm + OFF_WL);
        for (int i = tid; i < 192 * 64; i += 256) {
            const int o = i >> 6, cp = i & 63;
            WHs[o * 68 + cp] = g_Whb[i];
            WLs[o * 68 + cp] = g_Wlb[i];
        }
        if (tid < NOUT) ((float*)(sm + OFF_BIAS))[tid] = g_bias[tid];
    }
    {
        uint32_t* XHs = (uint32_t*)(sm + OFF_XH);
        uint32_t* XLs = (uint32_t*)(sm + OFF_XL);
        const float* xb = x + (size_t)b * CIN * S_TOT + s0;
        #pragma unroll 4
        for (int it = 0; it < 32; it++) {
            const int id = it * 256 + tid;
            const int s = id & 127, cp = id >> 7;
            const float v0 = xb[(size_t)(2 * cp) * S_TOT + s];
            const float v1 = xb[(size_t)(2 * cp + 1) * S_TOT + s];
            uint16_t h0, l0, h1, l1;
            bf16_split(v0, h0, l0);
            bf16_split(v1, h1, l1);
            XHs[s * 68 + cp] = ((uint32_t)h1 << 16) | h0;
            XLs[s * 68 + cp] = ((uint32_t)l1 << 16) | l0;
        }
    }
    __syncthreads();

    const int wo = wid >> 1, ws = wid & 1;
    const int m0 = wo * 48, n0 = ws * 64;
    const uint32_t smb = smem_u32(sm);

    const uint32_t a_off = (uint32_t)(m0 + (lane & 15)) * ROWB + ((lane >> 4) << 4);
    const uint32_t b_off = (uint32_t)(n0 + (lane & 7))  * ROWB + (((lane >> 3) & 1) << 4);

    float acc[96];
    #pragma unroll
    for (int i = 0; i < 96; i++) acc[i] = 0.f;

    {
        const uint32_t Ab[3] = { OFF_WH, OFF_WL, OFF_WH };
        const uint32_t Bb[3] = { OFF_XH, OFF_XH, OFF_XL };
        #pragma unroll
        for (int t = 0; t < 3; t++) {
            const uint32_t Aaddr = smb + Ab[t] + a_off;
            const uint32_t Baddr = smb + Bb[t] + b_off;
            #pragma unroll
            for (int ks = 0; ks < 8; ks++) {
                const uint32_t kb2 = (uint32_t)ks * 32;
                uint32_t a[3][4];
                #pragma unroll
                for (int mt = 0; mt < 3; mt++)
                    LDSM_X4(a[mt], Aaddr + (uint32_t)mt * 16 * ROWB + kb2);
                #pragma unroll
                for (int nt = 0; nt < 8; nt++) {
                    uint32_t b0, b1;
                    LDSM_X2(b0, b1, Baddr + (uint32_t)nt * 8 * ROWB + kb2);
                    #pragma unroll
                    for (int mt = 0; mt < 3; mt++)
                        mma_bf16(&acc[(mt * 8 + nt) * 4], a[mt], b0, b1);
                }
            }
        }
    }
    __syncthreads();   // XH/XL and WH/WL dead -> rsh / second-MMA staging

    const int g = lane >> 2, tig = lane & 3;
    const float* bias = (const float*)(sm + OFF_BIAS);
    float* rsh = (float*)sm;                        // [64][132] fp32, alias XH/XL
    uint16_t* sAh = (uint16_t*)(sm + OFF2_AH);      // [64][136] bf16 hi
    uint16_t* sAl = (uint16_t*)(sm + OFF2_AL);
    uint16_t* sEh = (uint16_t*)(sm + OFF2_EH);
    uint16_t* sEl = (uint16_t*)(sm + OFF2_EL);

    #pragma unroll
    for (int mt = 0; mt < 3; mt++) {
        #pragma unroll
        for (int half = 0; half < 2; half++) {
            const int rbase = m0 + mt * 16 + half * 8;
            const int r = rbase + g;
            const int cat = rbase >> 6;
            const float bv = bias[r];
            const int sl = n0 + 2 * tig;
            if (cat == 0) {
                // phi: stage into smem (bf16 split) for second MMA; no global write
                #pragma unroll
                for (int nt = 0; nt < 8; nt++) {
                    const float v0 = acc[(mt * 8 + nt) * 4 + half * 2 + 0] + bv;
                    const float v1 = acc[(mt * 8 + nt) * 4 + half * 2 + 1] + bv;
                    uint16_t h0, l0, h1, l1;
                    bf16_split(v0, h0, l0); bf16_split(v1, h1, l1);
                    const int off = r * 136 + sl + nt * 8;
                    *(uint32_t*)&sAh[off] = ((uint32_t)h1 << 16) | h0;
                    *(uint32_t*)&sAl[off] = ((uint32_t)l1 << 16) | l0;
                }
            } else if (cat == 1) {
                // theta: e -> g_B (+rowsum), e*Cm staged for second MMA
                float rs = 0.f;
                float* dst = g_B + ((size_t)(b * 64 + r - 64)) * S_TOT + s0 + sl;
                #pragma unroll
                for (int nt = 0; nt < 8; nt++) {
                    const float e0 = __expf(acc[(mt * 8 + nt) * 4 + half * 2 + 0] + bv);
                    const float e1 = __expf(acc[(mt * 8 + nt) * 4 + half * 2 + 1] + bv);
                    *(float2*)(dst + nt * 8) = make_float2(e0, e1);
                    rs += e0 + e1;
                    const float c0 = e0 * Csh[sl + nt * 8];
                    const float c1 = e1 * Csh[sl + nt * 8 + 1];
                    uint16_t h0, l0, h1, l1;
                    bf16_split(c0, h0, l0); bf16_split(c1, h1, l1);
                    const int off = (r - 64) * 136 + sl + nt * 8;
                    *(uint32_t*)&sEh[off] = ((uint32_t)h1 << 16) | h0;
                    *(uint32_t*)&sEl[off] = ((uint32_t)l1 << 16) | l0;
                }
                rs += __shfl_xor_sync(0xffffffffu, rs, 1);
                rs += __shfl_xor_sync(0xffffffffu, rs, 2);
                if (tig == 0) psh[r - 64][ws] = rs;
            } else {
                // rho logits -> rsh for channel softmax
                #pragma unroll
                for (int nt = 0; nt < 8; nt++) {
                    const float v0 = acc[(mt * 8 + nt) * 4 + half * 2 + 0] + bv;
                    const float v1 = acc[(mt * 8 + nt) * 4 + half * 2 + 1] + bv;
                    *(float2*)(rsh + (r - 128) * 132 + sl + nt * 8) = make_float2(v0, v1);
                }
            }
        }
    }
    __syncthreads();

    // ---- second MMA: P[64][64] = A @ (eC)^T over K=128 ----
    {
        const int m0b = (wid >> 1) * 16, n0b = (wid & 1) * 32;
        const uint32_t a_off2 = (uint32_t)(m0b + (lane & 15)) * ROWB + ((lane >> 4) << 4);
        const uint32_t b_off2 = (uint32_t)(n0b + (lane & 7))  * ROWB + (((lane >> 3) & 1) << 4);

        float acc2[16];
        #pragma unroll
        for (int i = 0; i < 16; i++) acc2[i] = 0.f;

        const uint32_t tA[3] = { OFF2_AH, OFF2_AL, OFF2_AH };
        const uint32_t tB[3] = { OFF2_EH, OFF2_EH, OFF2_EL };
        #pragma unroll
        for (int t = 0; t < 3; t++) {
            const uint32_t Aaddr = smb + tA[t] + a_off2;
            const uint32_t Baddr = smb + tB[t] + b_off2;
            #pragma unroll
            for (int ks = 0; ks < 8; ks++) {
                uint32_t a[4];
                LDSM_X4(a, Aaddr + (uint32_t)ks * 32);
                #pragma unroll
                for (int nt = 0; nt < 4; nt++) {
                    uint32_t b0, b1;
                    LDSM_X2(b0, b1, Baddr + (uint32_t)nt * 8 * ROWB + (uint32_t)ks * 32);
                    mma_bf16(&acc2[nt * 4], a, b0, b1);
                }
            }
        }
        float* P = g_Pab + ((size_t)(b * 128 + tile)) * 4096;
        #pragma unroll
        for (int nt = 0; nt < 4; nt++)
            #pragma unroll
            for (int half = 0; half < 2; half++) {
                const int row = m0b + half * 8 + g;
                const int col = n0b + nt * 8 + 2 * tig;
                *(float2*)(P + row * 64 + col) =
                    make_float2(acc2[nt * 4 + half * 2], acc2[nt * 4 + half * 2 + 1]);
            }
    }

    // ---- rho softmax + g_ps (no extra sync needed: disjoint smem, same threads)
    if (tid < 128) {
        const int scol = tid;
        float m = -1e30f;
        #pragma unroll 8
        for (int n = 0; n < 64; n++) m = fmaxf(m, rsh[n * 132 + scol]);
        float sum = 0.f;
        #pragma unroll 8
        for (int n = 0; n < 64; n++) {
            const float e = __expf(rsh[n * 132 + scol] - m);
            rsh[n * 132 + scol] = e;
            sum += e;
        }
        const float inv = 1.f / sum;
        uint32_t* vt = g_Vt + ((size_t)b * S_TOT + s0 + scol) * 64;
        #pragma unroll 8
        for (int n = 0; n < 64; n++) {
            const float v = rsh[n * 132 + scol] * inv;
            g_V[((size_t)(b * 64 + n)) * S_TOT + s0 + scol] = v;
            uint16_t h, l;
            bf16_split(v, h, l);
            vt[n] = ((uint32_t)l << 16) | h;
        }
    } else if (tid < 192) {
        const int o = tid - 128;
        g_ps[((size_t)(b * 128 + tile)) * 64 + o] = psh[o][0] + psh[o][1];
    }
}

// ---------------------------------------------------------------------------
// K3: attn = transpose(Bm*V); inv computed in-block from g_ps (esum fused).
// ---------------------------------------------------------------------------
__global__ void attn_kernel(float* __restrict__ attn_out)
{
    const int row = blockIdx.x >> 2;        // b*64+n
    const int hw0 = (blockIdx.x & 3) * 256;
    const int tid = threadIdx.x;
    const int bb = row >> 6, nn = row & 63;

    __shared__ float sh[256 * 20];
    __shared__ float sinv;

    const float4* e4 = (const float4*)(g_B + (size_t)row * S_TOT);
    const float4* v4 = (const float4*)(g_V + (size_t)row * S_TOT);

    #pragma unroll
    for (int k = 0; k < 4; k++) {
        const int id = k * 256 + tid;
        const int t  = id >> 6;
        const int f  = id & 63;
        const int si = (t << 10) + hw0 + f * 4;
        const float4 ev = e4[si >> 2];
        const float4 vv = v4[si >> 2];
        float* d = sh + (f * 4) * 20 + t;
        d[0]  = ev.x * vv.x;
        d[20] = ev.y * vv.y;
        d[40] = ev.z * vv.z;
        d[60] = ev.w * vv.w;
    }
    if (tid < 32) {
        float s = 0.f;
        const float* p = g_ps + (size_t)bb * 128 * 64 + nn;
        #pragma unroll
        for (int t = tid; t < 128; t += 32) s += p[t * 64];
        #pragma unroll
        for (int o = 16; o > 0; o >>= 1) s += __shfl_down_sync(0xffffffffu, s, o);
        if (tid == 0) sinv = 1.f / s;
    }
    __syncthreads();

    const float inv = sinv;
    float4* out = (float4*)(attn_out + ((size_t)row * HW + hw0) * T_DIM);
    #pragma unroll
    for (int k = 0; k < 4; k++) {
        const int id = k * 256 + tid;
        float4 v = *(const float4*)(sh + (id >> 2) * 20 + (id & 3) * 4);
        v.x *= inv; v.y *= inv; v.z *= inv; v.w *= inv;
        out[id] = v;
    }
}

// ---------------------------------------------------------------------------
// K4: reduce 128 AB_T partials per b, apply inv[n] (esum fused). grid 128.
// ---------------------------------------------------------------------------
__global__ void abred_kernel()
{
    const int bid = blockIdx.x, tid = threadIdx.x;
    const int b = bid >> 4, seg = bid & 15;
    __shared__ float invsh[64];

    {
        const int n = tid >> 2, q = tid & 3;
        float s = 0.f;
        const float* p = g_ps + (size_t)b * 128 * 64 + n;
        #pragma unroll
        for (int t = 0; t < 32; t++) s += p[(q * 32 + t) * 64];
        s += __shfl_xor_sync(0xffffffffu, s, 1);
        s += __shfl_xor_sync(0xffffffffu, s, 2);
        if (q == 0) invsh[n] = 1.f / s;
    }
    __syncthreads();

    const int m = seg * 4 + (tid >> 6), n = tid & 63;
    const float* P = g_Pab + (size_t)b * 128 * 4096 + m * 64 + n;
    float s = 0.f;
    #pragma unroll 8
    for (int t = 0; t < 128; t++) s += P[(size_t)t * 4096];
    g_AB[b * 4096 + m * 64 + n] = s * invsh[n];
}

// ---------------------------------------------------------------------------
// K5: Z = AB @ V via HMMA (proven R6 kernel).
// ---------------------------------------------------------------------------
#define Z_SAB  (64 * 72)
#define Z_SV   (128 * 72)
#define Z_SMEM ((2 * Z_SAB + 2 * Z_SV) * 2)

__global__ void __launch_bounds__(256)
z_kernel(float* __restrict__ Zout)
{
    extern __shared__ uint16_t zsm[];
    uint16_t* sABh = zsm;
    uint16_t* sABl = zsm + Z_SAB;
    uint16_t* sVh  = zsm + 2 * Z_SAB;
    uint16_t* sVl  = zsm + 2 * Z_SAB + Z_SV;

    const int b  = blockIdx.y;
    const int s0 = blockIdx.x * 128;
    const int tid = threadIdx.x, wid = tid >> 5, lane = tid & 31;

    for (int idx = tid; idx < 4096; idx += 256) {
        const int r = idx >> 6, k = idx & 63;
        uint16_t h, l;
        bf16_split(g_AB[b * 4096 + idx], h, l);
        sABh[r * 72 + k] = h; sABl[r * 72 + k] = l;
    }
    {
        const uint32_t* vt = g_Vt + ((size_t)b * S_TOT + s0) * 64;
        #pragma unroll 4
        for (int it = 0; it < 32; it++) {
            const int idx = it * 256 + tid;
            const int srow = idx >> 6, c = idx & 63;
            const uint32_t p = vt[srow * 64 + c];
            sVh[srow * 72 + c] = (uint16_t)p;
            sVl[srow * 72 + c] = (uint16_t)(p >> 16);
        }
    }
    __syncthreads();

    const int wm = wid >> 2, wn = wid & 3;
    const int m0 = wm * 32, n0 = wn * 32;
    const uint32_t sABhB = smem_u32(sABh), sABlB = smem_u32(sABl);
    const uint32_t sVhB  = smem_u32(sVh),  sVlB  = smem_u32(sVl);
    const uint32_t a_off = (uint32_t)(m0 + (lane & 15)) * 144 + ((lane >> 4) << 4);
    const uint32_t b_off = (uint32_t)(n0 + (lane & 7))  * 144 + (((lane >> 3) & 1) << 4);

    float acc[32];
    #pragma unroll
    for (int i = 0; i < 32; i++) acc[i] = 0.f;

    #pragma unroll
    for (int t = 0; t < 3; t++) {
        const uint32_t Aaddr = (t == 1 ? sABlB : sABhB) + a_off;
        const uint32_t Baddr = (t == 2 ? sVlB  : sVhB)  + b_off;
        #pragma unroll
        for (int ks = 0; ks < 4; ks++) {
            uint32_t a0[4], a1[4];
            LDSM_X4(a0, Aaddr + (uint32_t)ks * 32);
            LDSM_X4(a1, Aaddr + 16 * 144 + (uint32_t)ks * 32);
            #pragma unroll
            for (int nt = 0; nt < 4; nt++) {
                uint32_t b0, b1;
                LDSM_X2(b0, b1, Baddr + (uint32_t)nt * 8 * 144 + (uint32_t)ks * 32);
                mma_bf16(&acc[nt * 4], a0, b0, b1);
                mma_bf16(&acc[16 + nt * 4], a1, b0, b1);
            }
        }
    }

    const int g = lane >> 2, tig = lane & 3;
    #pragma unroll
    for (int mt = 0; mt < 2; mt++)
        #pragma unroll
        for (int nt = 0; nt < 4; nt++)
            #pragma unroll
            for (int half = 0; half < 2; half++) {
                const int row = m0 + mt * 16 + half * 8 + g;
                const int col = s0 + n0 + nt * 8 + 2 * tig;
                *(float2*)(Zout + ((size_t)(b * 64 + row)) * S_TOT + col) =
                    make_float2(acc[mt * 16 + nt * 4 + half * 2],
                                acc[mt * 16 + nt * 4 + half * 2 + 1]);
            }
}

// ---------------------------------------------------------------------------
extern "C" void kernel_launch(void* const* d_in, const int* in_sizes, int n_in,
                              void* d_out, int out_size)
{
    (void)in_sizes; (void)n_in; (void)out_size;
    const float* input = (const float*)d_in[0];
    const float* cond  = (const float*)d_in[1];
    const float* Wphi  = (const float*)d_in[2];
    const float* bphi  = (const float*)d_in[3];
    const float* Wth   = (const float*)d_in[4];
    const float* bth   = (const float*)d_in[5];
    const float* Wrho  = (const float*)d_in[6];
    const float* brho  = (const float*)d_in[7];
    const float* W1    = (const float*)d_in[8];
    const float* b1    = (const float*)d_in[9];
    const float* W2    = (const float*)d_in[10];
    const float* b2    = (const float*)d_in[11];

    float* Z    = (float*)d_out;
    float* attn = Z + (size_t)BATCH * 64 * S_TOT;

    cudaFuncSetAttribute(proj_mma_kernel,
                         cudaFuncAttributeMaxDynamicSharedMemorySize, PROJ_SMEM);
    cudaFuncSetAttribute(z_kernel,
                         cudaFuncAttributeMaxDynamicSharedMemorySize, Z_SMEM);

    cond_kernel<<<BATCH, 1024>>>(cond, W1, b1, W2, b2);          // 1
    prepA_kernel<<<24, 256>>>(Wphi, Wth, Wrho);                  // 2
    prepB_kernel<<<24, 256>>>(Wphi, bphi, Wth, bth, Wrho, brho); // 3
    proj_mma_kernel<<<dim3(128, BATCH), 256, PROJ_SMEM>>>(input);// 4 <- profiled
    attn_kernel<<<512 * 4, 256>>>(attn);                         // 5
    abred_kernel<<<128, 256>>>();                                // 6
    z_kernel<<<dim3(128, BATCH), 256, Z_SMEM>>>(Z);              // 7
}

// round 8
// speedup vs baseline: 2.0300x; 1.0511x over previous
#include <cuda_runtime.h>
#include <cuda_bf16.h>
#include <cstdint>

// ---------------------------------------------------------------------------
//   B=8, C=128, T=16, H=32, W=32  -> S = 16384, HW = 1024
//   M = N = 64, CS = 64.  Output: Z (8,64,16,32,32) ++ attn (8,64,32,32,16).
// ---------------------------------------------------------------------------
#define BATCH 8
#define CIN   128
#define S_TOT 16384
#define HW    1024
#define T_DIM 16
#define NOUT  192

// -------------------------- device scratch --------------------------------
__device__ float g_B [BATCH * 64 * S_TOT];        // exp(theta logits)
__device__ float g_V [BATCH * 64 * S_TOT];        // rho softmax (fp32, for attn)
__device__ uint32_t g_Vt[BATCH * S_TOT * 64];     // V transposed, packed bf16 hi|lo
__device__ float g_Cm[BATCH * HW];
__device__ float g_ps[BATCH * 128 * 64];          // per-tile theta exp sums
__device__ float g_Pab[BATCH * 128 * 64 * 64];    // AB_T per-tile partials (16MB)
__device__ float g_AB [BATCH * 64 * 64];
// weights pre-split to bf16 hi/lo, packed pairs of c
__device__ uint32_t g_Whb[NOUT * 64];
__device__ uint32_t g_Wlb[NOUT * 64];
__device__ float    g_bias[NOUT];

// ------------------------------ helpers -----------------------------------
__device__ __forceinline__ uint32_t smem_u32(const void* p) {
    uint32_t a;
    asm("{ .reg .u64 t; cvta.to.shared.u64 t, %1; cvt.u32.u64 %0, t; }"
        : "=r"(a) : "l"(p));
    return a;
}

#define LDSM_X4(r, addr) \
    asm volatile("ldmatrix.sync.aligned.m8n8.x4.shared.b16 {%0,%1,%2,%3}, [%4];" \
        : "=r"((r)[0]), "=r"((r)[1]), "=r"((r)[2]), "=r"((r)[3]) : "r"(addr))
#define LDSM_X2(r0, r1, addr) \
    asm volatile("ldmatrix.sync.aligned.m8n8.x2.shared.b16 {%0,%1}, [%2];" \
        : "=r"(r0), "=r"(r1) : "r"(addr))

__device__ __forceinline__ void mma_bf16(float* c, const uint32_t* a,
                                         uint32_t b0, uint32_t b1) {
    asm volatile(
        "mma.sync.aligned.m16n8k16.row.col.f32.bf16.bf16.f32 "
        "{%0,%1,%2,%3}, {%4,%5,%6,%7}, {%8,%9}, {%0,%1,%2,%3};"
        : "+f"(c[0]), "+f"(c[1]), "+f"(c[2]), "+f"(c[3])
        : "r"(a[0]), "r"(a[1]), "r"(a[2]), "r"(a[3]), "r"(b0), "r"(b1));
}

__device__ __forceinline__ void bf16_split(float v, uint16_t& h, uint16_t& l) {
    const __nv_bfloat16 hh = __float2bfloat16(v);
    const __nv_bfloat16 ll = __float2bfloat16(v - __bfloat162float(hh));
    h = __bfloat16_as_ushort(hh);
    l = __bfloat16_as_ushort(ll);
}

// ---------------------------------------------------------------------------
// K0: condition path.
// ---------------------------------------------------------------------------
__global__ void cond_kernel(const float* __restrict__ cond,
                            const float* __restrict__ W1, const float* __restrict__ b1,
                            const float* __restrict__ W2, const float* __restrict__ b2)
{
    const int b   = blockIdx.x;
    const int tid = threadIdx.x;
    __shared__ float cv[64], h1[64], red[1024];

    if (tid < 64) cv[tid] = cond[b * 64 + tid];
    __syncthreads();
    if (tid < 64) {
        float a = b1[tid];
        #pragma unroll 8
        for (int k = 0; k < 64; k++) a += cv[k] * W1[tid * 64 + k];
        h1[tid] = fmaxf(a, 0.f);
    }
    __syncthreads();
    float a = b2[tid];
    #pragma unroll 8
    for (int k = 0; k < 64; k++) a += h1[k] * W2[tid * 64 + k];
    a = fmaxf(a, 0.f);

    red[tid] = a; __syncthreads();
    for (int o = 512; o > 0; o >>= 1) {
        if (tid < o) red[tid] = fmaxf(red[tid], red[tid + o]);
        __syncthreads();
    }
    const float m = red[0]; __syncthreads();
    const float e = __expf(a - m);
    red[tid] = e; __syncthreads();
    for (int o = 512; o > 0; o >>= 1) {
        if (tid < o) red[tid] += red[tid + o];
        __syncthreads();
    }
    g_Cm[b * HW + tid] = e / red[0];
}

// ---------------------------------------------------------------------------
// prep (two launches so proj stays the 4th launch -> profiled).
// ---------------------------------------------------------------------------
__device__ __forceinline__ void prep_one(int i, const float* Wphi, const float* Wth,
                                         const float* Wrho)
{
    const int o = i >> 6, cp = i & 63;
    const float* Wsrc = o < 64 ? Wphi : (o < 128 ? Wth : Wrho);
    const int or_ = o & 63;
    const float w0 = Wsrc[or_ * 128 + cp * 2];
    const float w1 = Wsrc[or_ * 128 + cp * 2 + 1];
    uint16_t h0, l0, h1, l1;
    bf16_split(w0, h0, l0);
    bf16_split(w1, h1, l1);
    g_Whb[i] = ((uint32_t)h1 << 16) | h0;
    g_Wlb[i] = ((uint32_t)l1 << 16) | l0;
}

__global__ void prepA_kernel(const float* __restrict__ Wphi,
                             const float* __restrict__ Wth,
                             const float* __restrict__ Wrho)
{
    const int i = blockIdx.x * 256 + threadIdx.x;
    prep_one(i, Wphi, Wth, Wrho);
}

__global__ void prepB_kernel(const float* __restrict__ Wphi, const float* __restrict__ bphi,
                             const float* __restrict__ Wth,  const float* __restrict__ bth,
                             const float* __restrict__ Wrho, const float* __restrict__ brho)
{
    const int i = blockIdx.x * 256 + threadIdx.x;
    prep_one(6144 + i, Wphi, Wth, Wrho);
    if (i < NOUT)
        g_bias[i] = i < 64 ? bphi[i] : (i < 128 ? bth[i - 64] : brho[i - 128]);
}

// ---------------------------------------------------------------------------
// K1: tensor-core projection + fused AB_T partial.  512 threads / 16 warps:
// warp tile 48(o) x 32(s) -> acc[48]/thread, 16 warps/SM for latency hiding.
// ---------------------------------------------------------------------------
#define ROWB 272
#define OFF_XH 0
#define OFF_XL (128 * ROWB)
#define OFF_WH (2 * 128 * ROWB)
#define OFF_WL (2 * 128 * ROWB + 192 * ROWB)
#define OFF_BIAS (2 * 128 * ROWB + 2 * 192 * ROWB)
#define PROJ_SMEM (OFF_BIAS + 192 * 4)
// second-MMA operands (alias WH/WL, dead after main loop)
#define OFF2_AH (OFF_WH)
#define OFF2_AL (OFF_WH + 64 * ROWB)
#define OFF2_EH (OFF_WH + 2 * 64 * ROWB)
#define OFF2_EL (OFF_WH + 3 * 64 * ROWB)

__global__ void __launch_bounds__(512, 1)
proj_mma_kernel(const float* __restrict__ x)
{
    extern __shared__ char sm[];
    const int b = blockIdx.y, tile = blockIdx.x, s0 = tile * 128;
    const int tid = threadIdx.x, wid = tid >> 5, lane = tid & 31;

    __shared__ float psh[64][4];
    __shared__ float Csh[128];

    if (tid < 128) Csh[tid] = g_Cm[b * HW + ((s0 + tid) & (HW - 1))];

    {
        uint32_t* WHs = (uint32_t*)(sm + OFF_WH);
        uint32_t* WLs = (uint32_t*)(sm + OFF_WL);
        for (int i = tid; i < 192 * 64; i += 512) {
            const int o = i >> 6, cp = i & 63;
            WHs[o * 68 + cp] = g_Whb[i];
            WLs[o * 68 + cp] = g_Wlb[i];
        }
        if (tid < NOUT) ((float*)(sm + OFF_BIAS))[tid] = g_bias[tid];
    }
    {
        uint32_t* XHs = (uint32_t*)(sm + OFF_XH);
        uint32_t* XLs = (uint32_t*)(sm + OFF_XL);
        const float* xb = x + (size_t)b * CIN * S_TOT + s0;
        #pragma unroll 4
        for (int it = 0; it < 16; it++) {
            const int id = it * 512 + tid;           // 8192
            const int s = id & 127, cp = id >> 7;
            const float v0 = xb[(size_t)(2 * cp) * S_TOT + s];
            const float v1 = xb[(size_t)(2 * cp + 1) * S_TOT + s];
            uint16_t h0, l0, h1, l1;
            bf16_split(v0, h0, l0);
            bf16_split(v1, h1, l1);
            XHs[s * 68 + cp] = ((uint32_t)h1 << 16) | h0;
            XLs[s * 68 + cp] = ((uint32_t)l1 << 16) | l0;
        }
    }
    __syncthreads();

    const int wo = wid >> 2, ws = wid & 3;          // 4 x 4 warp grid
    const int m0 = wo * 48, n0 = ws * 32;
    const uint32_t smb = smem_u32(sm);

    const uint32_t a_off = (uint32_t)(m0 + (lane & 15)) * ROWB + ((lane >> 4) << 4);
    const uint32_t b_off = (uint32_t)(n0 + (lane & 7))  * ROWB + (((lane >> 3) & 1) << 4);

    float acc[48];
    #pragma unroll
    for (int i = 0; i < 48; i++) acc[i] = 0.f;

    {
        const uint32_t Ab[3] = { OFF_WH, OFF_WL, OFF_WH };
        const uint32_t Bb[3] = { OFF_XH, OFF_XH, OFF_XL };
        #pragma unroll
        for (int t = 0; t < 3; t++) {
            const uint32_t Aaddr = smb + Ab[t] + a_off;
            const uint32_t Baddr = smb + Bb[t] + b_off;
            #pragma unroll
            for (int ks = 0; ks < 8; ks++) {
                const uint32_t kb2 = (uint32_t)ks * 32;
                uint32_t a[3][4];
                #pragma unroll
                for (int mt = 0; mt < 3; mt++)
                    LDSM_X4(a[mt], Aaddr + (uint32_t)mt * 16 * ROWB + kb2);
                #pragma unroll
                for (int nt = 0; nt < 4; nt++) {
                    uint32_t b0, b1;
                    LDSM_X2(b0, b1, Baddr + (uint32_t)nt * 8 * ROWB + kb2);
                    #pragma unroll
                    for (int mt = 0; mt < 3; mt++)
                        mma_bf16(&acc[(mt * 4 + nt) * 4], a[mt], b0, b1);
                }
            }
        }
    }
    __syncthreads();   // XH/XL, WH/WL dead -> rsh / second-MMA staging

    const int g = lane >> 2, tig = lane & 3;
    const float* bias = (const float*)(sm + OFF_BIAS);
    float* rsh = (float*)sm;                        // [64][132] fp32, alias XH/XL
    uint16_t* sAh = (uint16_t*)(sm + OFF2_AH);      // [64][136] bf16
    uint16_t* sAl = (uint16_t*)(sm + OFF2_AL);
    uint16_t* sEh = (uint16_t*)(sm + OFF2_EH);
    uint16_t* sEl = (uint16_t*)(sm + OFF2_EL);

    #pragma unroll
    for (int mt = 0; mt < 3; mt++) {
        #pragma unroll
        for (int half = 0; half < 2; half++) {
            const int rbase = m0 + mt * 16 + half * 8;
            const int r = rbase + g;
            const int cat = rbase >> 6;
            const float bv = bias[r];
            const int sl = n0 + 2 * tig;
            if (cat == 0) {
                #pragma unroll
                for (int nt = 0; nt < 4; nt++) {
                    const float v0 = acc[(mt * 4 + nt) * 4 + half * 2 + 0] + bv;
                    const float v1 = acc[(mt * 4 + nt) * 4 + half * 2 + 1] + bv;
                    uint16_t h0, l0, h1, l1;
                    bf16_split(v0, h0, l0); bf16_split(v1, h1, l1);
                    const int off = r * 136 + sl + nt * 8;
                    *(uint32_t*)&sAh[off] = ((uint32_t)h1 << 16) | h0;
                    *(uint32_t*)&sAl[off] = ((uint32_t)l1 << 16) | l0;
                }
            } else if (cat == 1) {
                float rs = 0.f;
                float* dst = g_B + ((size_t)(b * 64 + r - 64)) * S_TOT + s0 + sl;
                #pragma unroll
                for (int nt = 0; nt < 4; nt++) {
                    const float e0 = __expf(acc[(mt * 4 + nt) * 4 + half * 2 + 0] + bv);
                    const float e1 = __expf(acc[(mt * 4 + nt) * 4 + half * 2 + 1] + bv);
                    *(float2*)(dst + nt * 8) = make_float2(e0, e1);
                    rs += e0 + e1;
                    const float c0 = e0 * Csh[sl + nt * 8];
                    const float c1 = e1 * Csh[sl + nt * 8 + 1];
                    uint16_t h0, l0, h1, l1;
                    bf16_split(c0, h0, l0); bf16_split(c1, h1, l1);
                    const int off = (r - 64) * 136 + sl + nt * 8;
                    *(uint32_t*)&sEh[off] = ((uint32_t)h1 << 16) | h0;
                    *(uint32_t*)&sEl[off] = ((uint32_t)l1 << 16) | l0;
                }
                rs += __shfl_xor_sync(0xffffffffu, rs, 1);
                rs += __shfl_xor_sync(0xffffffffu, rs, 2);
                if (tig == 0) psh[r - 64][ws] = rs;
            } else {
                #pragma unroll
                for (int nt = 0; nt < 4; nt++) {
                    const float v0 = acc[(mt * 4 + nt) * 4 + half * 2 + 0] + bv;
                    const float v1 = acc[(mt * 4 + nt) * 4 + half * 2 + 1] + bv;
                    *(float2*)(rsh + (r - 128) * 132 + sl + nt * 8) = make_float2(v0, v1);
                }
            }
        }
    }
    __syncthreads();

    // ---- second MMA: P[64][64] = A @ (eC)^T over K=128, 16 warps 16x16 ----
    {
        const int m0b = (wid >> 2) * 16, n0b = (wid & 3) * 16;
        const uint32_t a_off2 = (uint32_t)(m0b + (lane & 15)) * ROWB + ((lane >> 4) << 4);
        const uint32_t b_off2 = (uint32_t)(n0b + (lane & 7))  * ROWB + (((lane >> 3) & 1) << 4);

        float acc2[8];
        #pragma unroll
        for (int i = 0; i < 8; i++) acc2[i] = 0.f;

        const uint32_t tA[3] = { OFF2_AH, OFF2_AL, OFF2_AH };
        const uint32_t tB[3] = { OFF2_EH, OFF2_EH, OFF2_EL };
        #pragma unroll
        for (int t = 0; t < 3; t++) {
            const uint32_t Aaddr = smb + tA[t] + a_off2;
            const uint32_t Baddr = smb + tB[t] + b_off2;
            #pragma unroll
            for (int ks = 0; ks < 8; ks++) {
                uint32_t a[4];
                LDSM_X4(a, Aaddr + (uint32_t)ks * 32);
                #pragma unroll
                for (int nt = 0; nt < 2; nt++) {
                    uint32_t b0, b1;
                    LDSM_X2(b0, b1, Baddr + (uint32_t)nt * 8 * ROWB + (uint32_t)ks * 32);
                    mma_bf16(&acc2[nt * 4], a, b0, b1);
                }
            }
        }
        float* P = g_Pab + ((size_t)(b * 128 + tile)) * 4096;
        #pragma unroll
        for (int nt = 0; nt < 2; nt++)
            #pragma unroll
            for (int half = 0; half < 2; half++) {
                const int row = m0b + half * 8 + g;
                const int col = n0b + nt * 8 + 2 * tig;
                *(float2*)(P + row * 64 + col) =
                    make_float2(acc2[nt * 4 + half * 2], acc2[nt * 4 + half * 2 + 1]);
            }
    }

    // ---- rho softmax + g_ps ----
    if (tid < 128) {
        const int scol = tid;
        float m = -1e30f;
        #pragma unroll 8
        for (int n = 0; n < 64; n++) m = fmaxf(m, rsh[n * 132 + scol]);
        float sum = 0.f;
        #pragma unroll 8
        for (int n = 0; n < 64; n++) {
            const float e = __expf(rsh[n * 132 + scol] - m);
            rsh[n * 132 + scol] = e;
            sum += e;
        }
        const float inv = 1.f / sum;
        uint32_t* vt = g_Vt + ((size_t)b * S_TOT + s0 + scol) * 64;
        #pragma unroll 8
        for (int n = 0; n < 64; n++) {
            const float v = rsh[n * 132 + scol] * inv;
            g_V[((size_t)(b * 64 + n)) * S_TOT + s0 + scol] = v;
            uint16_t h, l;
            bf16_split(v, h, l);
            vt[n] = ((uint32_t)l << 16) | h;
        }
    } else if (tid < 192) {
        const int o = tid - 128;
        g_ps[((size_t)(b * 128 + tile)) * 64 + o] =
            psh[o][0] + psh[o][1] + psh[o][2] + psh[o][3];
    }
}

// ---------------------------------------------------------------------------
// K3: attn = transpose(Bm*V); inv computed in-block from g_ps.
// ---------------------------------------------------------------------------
__global__ void attn_kernel(float* __restrict__ attn_out)
{
    const int row = blockIdx.x >> 2;        // b*64+n
    const int hw0 = (blockIdx.x & 3) * 256;
    const int tid = threadIdx.x;
    const int bb = row >> 6, nn = row & 63;

    __shared__ float sh[256 * 20];
    __shared__ float sinv;

    const float4* e4 = (const float4*)(g_B + (size_t)row * S_TOT);
    const float4* v4 = (const float4*)(g_V + (size_t)row * S_TOT);

    #pragma unroll
    for (int k = 0; k < 4; k++) {
        const int id = k * 256 + tid;
        const int t  = id >> 6;
        const int f  = id & 63;
        const int si = (t << 10) + hw0 + f * 4;
        const float4 ev = e4[si >> 2];
        const float4 vv = v4[si >> 2];
        float* d = sh + (f * 4) * 20 + t;
        d[0]  = ev.x * vv.x;
        d[20] = ev.y * vv.y;
        d[40] = ev.z * vv.z;
        d[60] = ev.w * vv.w;
    }
    if (tid < 32) {
        float s = 0.f;
        const float* p = g_ps + (size_t)bb * 128 * 64 + nn;
        #pragma unroll
        for (int t = tid; t < 128; t += 32) s += p[t * 64];
        #pragma unroll
        for (int o = 16; o > 0; o >>= 1) s += __shfl_down_sync(0xffffffffu, s, o);
        if (tid == 0) sinv = 1.f / s;
    }
    __syncthreads();

    const float inv = sinv;
    float4* out = (float4*)(attn_out + ((size_t)row * HW + hw0) * T_DIM);
    #pragma unroll
    for (int k = 0; k < 4; k++) {
        const int id = k * 256 + tid;
        float4 v = *(const float4*)(sh + (id >> 2) * 20 + (id & 3) * 4);
        v.x *= inv; v.y *= inv; v.z *= inv; v.w *= inv;
        out[id] = v;
    }
}

// ---------------------------------------------------------------------------
// K4: reduce 128 AB_T partials per b, apply inv[n]. grid 128.
// ---------------------------------------------------------------------------
__global__ void abred_kernel()
{
    const int bid = blockIdx.x, tid = threadIdx.x;
    const int b = bid >> 4, seg = bid & 15;
    __shared__ float invsh[64];

    {
        const int n = tid >> 2, q = tid & 3;
        float s = 0.f;
        const float* p = g_ps + (size_t)b * 128 * 64 + n;
        #pragma unroll
        for (int t = 0; t < 32; t++) s += p[(q * 32 + t) * 64];
        s += __shfl_xor_sync(0xffffffffu, s, 1);
        s += __shfl_xor_sync(0xffffffffu, s, 2);
        if (q == 0) invsh[n] = 1.f / s;
    }
    __syncthreads();

    const int m = seg * 4 + (tid >> 6), n = tid & 63;
    const float* P = g_Pab + (size_t)b * 128 * 4096 + m * 64 + n;
    float s = 0.f;
    #pragma unroll 8
    for (int t = 0; t < 128; t++) s += P[(size_t)t * 4096];
    g_AB[b * 4096 + m * 64 + n] = s * invsh[n];
}

// ---------------------------------------------------------------------------
// K5: Z = AB @ V via HMMA.
// ---------------------------------------------------------------------------
#define Z_SAB  (64 * 72)
#define Z_SV   (128 * 72)
#define Z_SMEM ((2 * Z_SAB + 2 * Z_SV) * 2)

__global__ void __launch_bounds__(256)
z_kernel(float* __restrict__ Zout)
{
    extern __shared__ uint16_t zsm[];
    uint16_t* sABh = zsm;
    uint16_t* sABl = zsm + Z_SAB;
    uint16_t* sVh  = zsm + 2 * Z_SAB;
    uint16_t* sVl  = zsm + 2 * Z_SAB + Z_SV;

    const int b  = blockIdx.y;
    const int s0 = blockIdx.x * 128;
    const int tid = threadIdx.x, wid = tid >> 5, lane = tid & 31;

    for (int idx = tid; idx < 4096; idx += 256) {
        const int r = idx >> 6, k = idx & 63;
        uint16_t h, l;
        bf16_split(g_AB[b * 4096 + idx], h, l);
        sABh[r * 72 + k] = h; sABl[r * 72 + k] = l;
    }
    {
        const uint32_t* vt = g_Vt + ((size_t)b * S_TOT + s0) * 64;
        #pragma unroll 4
        for (int it = 0; it < 32; it++) {
            const int idx = it * 256 + tid;
            const int srow = idx >> 6, c = idx & 63;
            const uint32_t p = vt[srow * 64 + c];
            sVh[srow * 72 + c] = (uint16_t)p;
            sVl[srow * 72 + c] = (uint16_t)(p >> 16);
        }
    }
    __syncthreads();

    const int wm = wid >> 2, wn = wid & 3;
    const int m0 = wm * 32, n0 = wn * 32;
    const uint32_t sABhB = smem_u32(sABh), sABlB = smem_u32(sABl);
    const uint32_t sVhB  = smem_u32(sVh),  sVlB  = smem_u32(sVl);
    const uint32_t a_off = (uint32_t)(m0 + (lane & 15)) * 144 + ((lane >> 4) << 4);
    const uint32_t b_off = (uint32_t)(n0 + (lane & 7))  * 144 + (((lane >> 3) & 1) << 4);

    float acc[32];
    #pragma unroll
    for (int i = 0; i < 32; i++) acc[i] = 0.f;

    #pragma unroll
    for (int t = 0; t < 3; t++) {
        const uint32_t Aaddr = (t == 1 ? sABlB : sABhB) + a_off;
        const uint32_t Baddr = (t == 2 ? sVlB  : sVhB)  + b_off;
        #pragma unroll
        for (int ks = 0; ks < 4; ks++) {
            uint32_t a0[4], a1[4];
            LDSM_X4(a0, Aaddr + (uint32_t)ks * 32);
            LDSM_X4(a1, Aaddr + 16 * 144 + (uint32_t)ks * 32);
            #pragma unroll
            for (int nt = 0; nt < 4; nt++) {
                uint32_t b0, b1;
                LDSM_X2(b0, b1, Baddr + (uint32_t)nt * 8 * 144 + (uint32_t)ks * 32);
                mma_bf16(&acc[nt * 4], a0, b0, b1);
                mma_bf16(&acc[16 + nt * 4], a1, b0, b1);
            }
        }
    }

    const int g = lane >> 2, tig = lane & 3;
    #pragma unroll
    for (int mt = 0; mt < 2; mt++)
        #pragma unroll
        for (int nt = 0; nt < 4; nt++)
            #pragma unroll
            for (int half = 0; half < 2; half++) {
                const int row = m0 + mt * 16 + half * 8 + g;
                const int col = s0 + n0 + nt * 8 + 2 * tig;
                *(float2*)(Zout + ((size_t)(b * 64 + row)) * S_TOT + col) =
                    make_float2(acc[mt * 16 + nt * 4 + half * 2],
                                acc[mt * 16 + nt * 4 + half * 2 + 1]);
            }
}

// ---------------------------------------------------------------------------
extern "C" void kernel_launch(void* const* d_in, const int* in_sizes, int n_in,
                              void* d_out, int out_size)
{
    (void)in_sizes; (void)n_in; (void)out_size;
    const float* input = (const float*)d_in[0];
    const float* cond  = (const float*)d_in[1];
    const float* Wphi  = (const float*)d_in[2];
    const float* bphi  = (const float*)d_in[3];
    const float* Wth   = (const float*)d_in[4];
    const float* bth   = (const float*)d_in[5];
    const float* Wrho  = (const float*)d_in[6];
    const float* brho  = (const float*)d_in[7];
    const float* W1    = (const float*)d_in[8];
    const float* b1    = (const float*)d_in[9];
    const float* W2    = (const float*)d_in[10];
    const float* b2    = (const float*)d_in[11];

    float* Z    = (float*)d_out;
    float* attn = Z + (size_t)BATCH * 64 * S_TOT;

    cudaFuncSetAttribute(proj_mma_kernel,
                         cudaFuncAttributeMaxDynamicSharedMemorySize, PROJ_SMEM);
    cudaFuncSetAttribute(z_kernel,
                         cudaFuncAttributeMaxDynamicSharedMemorySize, Z_SMEM);

    cond_kernel<<<BATCH, 1024>>>(cond, W1, b1, W2, b2);          // 1
    prepA_kernel<<<24, 256>>>(Wphi, Wth, Wrho);                  // 2
    prepB_kernel<<<24, 256>>>(Wphi, bphi, Wth, bth, Wrho, brho); // 3
    proj_mma_kernel<<<dim3(128, BATCH), 512, PROJ_SMEM>>>(input);// 4 <- profiled
    attn_kernel<<<512 * 4, 256>>>(attn);                         // 5
    abred_kernel<<<128, 256>>>();                                // 6
    z_kernel<<<dim3(128, BATCH), 256, Z_SMEM>>>(Z);              // 7
}